// round 1
// baseline (speedup 1.0000x reference)
#include <cuda_runtime.h>
#include <math.h>

#define NTOK 4096
#define HDIM 1024
#define NEXP 16
#define IDIM 512
#define ISH  2048
#define TOPK 4

// ---------------- scratch (device globals; no allocation APIs) ----------------
__device__ float g_sact[(size_t)NTOK * ISH];          // shared-expert SwiGLU act [N, IS]  (32MB)
__device__ float g_eact[(size_t)NTOK * TOPK * IDIM];  // expert SwiGLU act, row = token*4+slot (32MB)
__device__ int   g_cnt[NEXP];                         // tokens per expert
__device__ int   g_list[NEXP * NTOK];                 // per-expert entry list (entry = token*4+slot)
__device__ float g_topw[NTOK * TOPK];                 // renormalized top-k weights
__device__ float g_gatesc[NTOK];                      // sigmoid(h . shared_expert_gate_w)

// ---------------- setup: reset counters, write constant aux loss ----------------
__global__ void setup_kernel(float* out, int out_size) {
    int t = threadIdx.x;
    if (t < NEXP) g_cnt[t] = 0;
    if (t == 0) {
        // aux_loss = E * sum(ft) * (sum(softmax)/N) = 16.0 analytically
        for (int i = NTOK * HDIM; i < out_size; i++) out[i] = (float)NEXP;
    }
}

// ---------------- router: logits -> softmax -> top-4 -> scatter ----------------
__global__ void router_kernel(const float* __restrict__ h,
                              const float* __restrict__ rw,
                              const float* __restrict__ egw) {
    int n    = blockIdx.x;
    int tid  = threadIdx.x;     // 128 threads
    int lane = tid & 31;
    int w    = tid >> 5;

    __shared__ float hs[HDIM];
    __shared__ float logits[NEXP + 1];

    const float4* hp  = (const float4*)(h + (size_t)n * HDIM);
    float4*       hs4 = (float4*)hs;
    for (int i = tid; i < HDIM / 4; i += 128) hs4[i] = hp[i];
    __syncthreads();

    for (int e = w; e < NEXP + 1; e += 4) {
        const float* wr = (e < NEXP) ? (rw + (size_t)e * HDIM) : egw;
        float s = 0.f;
        for (int i = lane; i < HDIM; i += 32) s += hs[i] * wr[i];
        for (int o = 16; o > 0; o >>= 1) s += __shfl_down_sync(0xffffffffu, s, o);
        if (lane == 0) logits[e] = s;
    }
    __syncthreads();

    if (tid == 0) {
        float mx = -1e30f;
        for (int e = 0; e < NEXP; e++) mx = fmaxf(mx, logits[e]);
        float p[NEXP];
        float den = 0.f;
        for (int e = 0; e < NEXP; e++) { p[e] = expf(logits[e] - mx); den += p[e]; }
        float inv = 1.f / den;
        for (int e = 0; e < NEXP; e++) p[e] *= inv;

        int   sel[TOPK];
        float sv[TOPK];
        float ssum = 0.f;
        for (int k = 0; k < TOPK; k++) {
            int bi = 0; float bv = -1.f;
            for (int e = 0; e < NEXP; e++)
                if (p[e] > bv) { bv = p[e]; bi = e; }
            sel[k] = bi; sv[k] = bv; ssum += bv; p[bi] = -2.f;
        }
        float rinv = 1.f / ssum;
        for (int k = 0; k < TOPK; k++) {
            int entry = n * TOPK + k;
            g_topw[entry] = sv[k] * rinv;
            int pos = atomicAdd(&g_cnt[sel[k]], 1);
            g_list[sel[k] * NTOK + pos] = entry;
        }
        g_gatesc[n] = 1.f / (1.f + expf(-logits[NEXP]));
    }
}

// ============================================================================
// GEMM kernels. All GEMMs here are NT with K contiguous for both operands:
// C[m,n] = dot(A[m, :K], B[n, :K]).
// Dual variant computes gate and up tiles simultaneously, fuses silu.
// ============================================================================

// ---- shared expert gate/up:  g_sact[m,j] = silu(h.Wg[j]) * (h.Wu[j]) ----
__global__ __launch_bounds__(256) void shared_gemm1(const float* __restrict__ A,
                                                    const float* __restrict__ Wg,
                                                    const float* __restrict__ Wu) {
    __shared__ float As[16][64];
    __shared__ float B1s[16][64];
    __shared__ float B2s[16][64];
    const int tid = threadIdx.x;
    const int tx = tid & 15, ty = tid >> 4;
    const int row0 = blockIdx.y * 64, col0 = blockIdx.x * 64;
    const int lr = tid >> 2, lk = (tid & 3) * 4;

    const float* Ap  = A  + (size_t)(row0 + lr) * HDIM + lk;
    const float* B1p = Wg + (size_t)(col0 + lr) * HDIM + lk;
    const float* B2p = Wu + (size_t)(col0 + lr) * HDIM + lk;

    float acc1[4][4] = {}, acc2[4][4] = {};

    for (int k0 = 0; k0 < HDIM; k0 += 16) {
        float4 av = *(const float4*)(Ap + k0);
        float4 b1 = *(const float4*)(B1p + k0);
        float4 b2 = *(const float4*)(B2p + k0);
        As[lk + 0][lr] = av.x; As[lk + 1][lr] = av.y; As[lk + 2][lr] = av.z; As[lk + 3][lr] = av.w;
        B1s[lk + 0][lr] = b1.x; B1s[lk + 1][lr] = b1.y; B1s[lk + 2][lr] = b1.z; B1s[lk + 3][lr] = b1.w;
        B2s[lk + 0][lr] = b2.x; B2s[lk + 1][lr] = b2.y; B2s[lk + 2][lr] = b2.z; B2s[lk + 3][lr] = b2.w;
        __syncthreads();
#pragma unroll
        for (int kk = 0; kk < 16; kk++) {
            float4 a = *(const float4*)&As[kk][ty * 4];
            float4 x = *(const float4*)&B1s[kk][tx * 4];
            float4 y = *(const float4*)&B2s[kk][tx * 4];
            float ar[4] = {a.x, a.y, a.z, a.w};
            float xr[4] = {x.x, x.y, x.z, x.w};
            float yr[4] = {y.x, y.y, y.z, y.w};
#pragma unroll
            for (int i = 0; i < 4; i++)
#pragma unroll
                for (int j = 0; j < 4; j++) {
                    acc1[i][j] += ar[i] * xr[j];
                    acc2[i][j] += ar[i] * yr[j];
                }
        }
        __syncthreads();
    }
#pragma unroll
    for (int i = 0; i < 4; i++) {
        int r = row0 + ty * 4 + i;
#pragma unroll
        for (int j = 0; j < 4; j++) {
            int c = col0 + tx * 4 + j;
            float g = acc1[i][j], u = acc2[i][j];
            g_sact[(size_t)r * ISH + c] = g / (1.f + expf(-g)) * u;
        }
    }
}

// ---- shared expert down:  out[m,c] = gatesc[m] * (g_sact[m,:] . Wd[c,:]) ----
__global__ __launch_bounds__(256) void shared_gemm2(const float* __restrict__ Wd,
                                                    float* __restrict__ out) {
    __shared__ float As[16][64];
    __shared__ float Bs[16][128];
    const int tid = threadIdx.x;
    const int tx = tid & 15, ty = tid >> 4;
    const int row0 = blockIdx.y * 64, col0 = blockIdx.x * 128;
    const int lr = tid >> 2, lk = (tid & 3) * 4;

    const float* Ap = g_sact + (size_t)(row0 + lr) * ISH + lk;
    float acc[4][8] = {};

    for (int k0 = 0; k0 < ISH; k0 += 16) {
        float4 av = *(const float4*)(Ap + k0);
        As[lk + 0][lr] = av.x; As[lk + 1][lr] = av.y; As[lk + 2][lr] = av.z; As[lk + 3][lr] = av.w;
#pragma unroll
        for (int q = tid; q < 512; q += 256) {
            int br = q >> 2, bk = (q & 3) * 4;
            float4 bv = *(const float4*)(Wd + (size_t)(col0 + br) * ISH + k0 + bk);
            Bs[bk + 0][br] = bv.x; Bs[bk + 1][br] = bv.y; Bs[bk + 2][br] = bv.z; Bs[bk + 3][br] = bv.w;
        }
        __syncthreads();
#pragma unroll
        for (int kk = 0; kk < 16; kk++) {
            float4 a  = *(const float4*)&As[kk][ty * 4];
            float4 b0 = *(const float4*)&Bs[kk][tx * 8];
            float4 b1 = *(const float4*)&Bs[kk][tx * 8 + 4];
            float ar[4] = {a.x, a.y, a.z, a.w};
            float br_[8] = {b0.x, b0.y, b0.z, b0.w, b1.x, b1.y, b1.z, b1.w};
#pragma unroll
            for (int i = 0; i < 4; i++)
#pragma unroll
                for (int j = 0; j < 8; j++) acc[i][j] += ar[i] * br_[j];
        }
        __syncthreads();
    }
#pragma unroll
    for (int i = 0; i < 4; i++) {
        int r = row0 + ty * 4 + i;
        float gs = g_gatesc[r];
#pragma unroll
        for (int j = 0; j < 8; j++) {
            int c = col0 + tx * 8 + j;
            out[(size_t)r * HDIM + c] = gs * acc[i][j];
        }
    }
}

// ---- experts gate/up (grouped, gathered rows):  g_eact[entry, c] = silu(g)*u ----
__global__ __launch_bounds__(256) void expert_gemm1(const float* __restrict__ h,
                                                    const float* __restrict__ gup) {
    const int e = blockIdx.z;
    const int cnt = g_cnt[e];
    const int m0 = blockIdx.y * 64;
    if (m0 >= cnt) return;

    __shared__ float As[16][64];
    __shared__ float B1s[16][64];
    __shared__ float B2s[16][64];
    const int tid = threadIdx.x;
    const int tx = tid & 15, ty = tid >> 4;
    const int col0 = blockIdx.x * 64;
    const int lr = tid >> 2, lk = (tid & 3) * 4;

    const int myrow = m0 + lr;
    const bool valid = (myrow < cnt);
    const float* Ap = h;  // dummy
    if (valid) {
        int entry = g_list[e * NTOK + myrow];
        Ap = h + (size_t)(entry >> 2) * HDIM + lk;
    }
    const float* Bb  = gup + (size_t)e * (2 * IDIM) * HDIM;
    const float* B1p = Bb + (size_t)(col0 + lr) * HDIM + lk;
    const float* B2p = Bb + (size_t)(IDIM + col0 + lr) * HDIM + lk;

    float acc1[4][4] = {}, acc2[4][4] = {};

    for (int k0 = 0; k0 < HDIM; k0 += 16) {
        float4 av = valid ? *(const float4*)(Ap + k0) : make_float4(0.f, 0.f, 0.f, 0.f);
        float4 b1 = *(const float4*)(B1p + k0);
        float4 b2 = *(const float4*)(B2p + k0);
        As[lk + 0][lr] = av.x; As[lk + 1][lr] = av.y; As[lk + 2][lr] = av.z; As[lk + 3][lr] = av.w;
        B1s[lk + 0][lr] = b1.x; B1s[lk + 1][lr] = b1.y; B1s[lk + 2][lr] = b1.z; B1s[lk + 3][lr] = b1.w;
        B2s[lk + 0][lr] = b2.x; B2s[lk + 1][lr] = b2.y; B2s[lk + 2][lr] = b2.z; B2s[lk + 3][lr] = b2.w;
        __syncthreads();
#pragma unroll
        for (int kk = 0; kk < 16; kk++) {
            float4 a = *(const float4*)&As[kk][ty * 4];
            float4 x = *(const float4*)&B1s[kk][tx * 4];
            float4 y = *(const float4*)&B2s[kk][tx * 4];
            float ar[4] = {a.x, a.y, a.z, a.w};
            float xr[4] = {x.x, x.y, x.z, x.w};
            float yr[4] = {y.x, y.y, y.z, y.w};
#pragma unroll
            for (int i = 0; i < 4; i++)
#pragma unroll
                for (int j = 0; j < 4; j++) {
                    acc1[i][j] += ar[i] * xr[j];
                    acc2[i][j] += ar[i] * yr[j];
                }
        }
        __syncthreads();
    }
#pragma unroll
    for (int i = 0; i < 4; i++) {
        int r = m0 + ty * 4 + i;
        if (r < cnt) {
            int entry = g_list[e * NTOK + r];
#pragma unroll
            for (int j = 0; j < 4; j++) {
                int c = col0 + tx * 4 + j;
                float g = acc1[i][j], u = acc2[i][j];
                g_eact[(size_t)entry * IDIM + c] = g / (1.f + expf(-g)) * u;
            }
        }
    }
}

// ---- experts down (grouped):  out[token,c] += w * (g_eact[entry,:] . Wd[c,:]) ----
__global__ __launch_bounds__(256) void expert_gemm2(const float* __restrict__ dwn,
                                                    float* __restrict__ out) {
    const int e = blockIdx.z;
    const int cnt = g_cnt[e];
    const int m0 = blockIdx.y * 64;
    if (m0 >= cnt) return;

    __shared__ float As[16][64];
    __shared__ float Bs[16][128];
    const int tid = threadIdx.x;
    const int tx = tid & 15, ty = tid >> 4;
    const int col0 = blockIdx.x * 128;
    const int lr = tid >> 2, lk = (tid & 3) * 4;

    const int myrow = m0 + lr;
    const bool valid = (myrow < cnt);
    const float* Ap = g_eact;  // dummy
    if (valid) {
        int entry = g_list[e * NTOK + myrow];
        Ap = g_eact + (size_t)entry * IDIM + lk;
    }
    const float* Bb = dwn + (size_t)e * HDIM * IDIM;

    float acc[4][8] = {};

    for (int k0 = 0; k0 < IDIM; k0 += 16) {
        float4 av = valid ? *(const float4*)(Ap + k0) : make_float4(0.f, 0.f, 0.f, 0.f);
        As[lk + 0][lr] = av.x; As[lk + 1][lr] = av.y; As[lk + 2][lr] = av.z; As[lk + 3][lr] = av.w;
#pragma unroll
        for (int q = tid; q < 512; q += 256) {
            int br = q >> 2, bk = (q & 3) * 4;
            float4 bv = *(const float4*)(Bb + (size_t)(col0 + br) * IDIM + k0 + bk);
            Bs[bk + 0][br] = bv.x; Bs[bk + 1][br] = bv.y; Bs[bk + 2][br] = bv.z; Bs[bk + 3][br] = bv.w;
        }
        __syncthreads();
#pragma unroll
        for (int kk = 0; kk < 16; kk++) {
            float4 a  = *(const float4*)&As[kk][ty * 4];
            float4 b0 = *(const float4*)&Bs[kk][tx * 8];
            float4 b1 = *(const float4*)&Bs[kk][tx * 8 + 4];
            float ar[4] = {a.x, a.y, a.z, a.w};
            float br_[8] = {b0.x, b0.y, b0.z, b0.w, b1.x, b1.y, b1.z, b1.w};
#pragma unroll
            for (int i = 0; i < 4; i++)
#pragma unroll
                for (int j = 0; j < 8; j++) acc[i][j] += ar[i] * br_[j];
        }
        __syncthreads();
    }
#pragma unroll
    for (int i = 0; i < 4; i++) {
        int r = m0 + ty * 4 + i;
        if (r < cnt) {
            int entry = g_list[e * NTOK + r];
            int token = entry >> 2;
            float w = g_topw[entry];
#pragma unroll
            for (int j = 0; j < 8; j++) {
                int c = col0 + tx * 8 + j;
                atomicAdd(&out[(size_t)token * HDIM + c], w * acc[i][j]);
            }
        }
    }
}

// ---------------------------------------------------------------------------
extern "C" void kernel_launch(void* const* d_in, const int* in_sizes, int n_in,
                              void* d_out, int out_size) {
    const float* h    = (const float*)d_in[0];  // [B,S,H]
    const float* rw   = (const float*)d_in[1];  // [E,H]
    const float* gup  = (const float*)d_in[2];  // [E,2I,H]
    const float* dwn  = (const float*)d_in[3];  // [E,H,I]
    const float* sgw  = (const float*)d_in[4];  // [IS,H]
    const float* suw  = (const float*)d_in[5];  // [IS,H]
    const float* sdw  = (const float*)d_in[6];  // [H,IS]
    const float* segw = (const float*)d_in[7];  // [1,H]
    float* out = (float*)d_out;

    setup_kernel<<<1, 32>>>(out, out_size);
    router_kernel<<<NTOK, 128>>>(h, rw, segw);
    shared_gemm1<<<dim3(ISH / 64, NTOK / 64), 256>>>(h, sgw, suw);
    shared_gemm2<<<dim3(HDIM / 128, NTOK / 64), 256>>>(sdw, out);
    expert_gemm1<<<dim3(IDIM / 64, NTOK / 64, NEXP), 256>>>(h, gup);
    expert_gemm2<<<dim3(HDIM / 128, NTOK / 64, NEXP), 256>>>(dwn, out);
}

// round 3
// speedup vs baseline: 2.4342x; 2.4342x over previous
#include <cuda_runtime.h>
#include <cstdint>
#include <math.h>

#define NTOK 4096
#define HDIM 1024
#define NEXP 16
#define IDIM 512
#define ISH  2048
#define TOPK 4

#define PAD   36
#define TILEF (128 * PAD)   // floats per 128x32 staged tile (padded)

// ---------------- scratch (device globals; no allocation APIs) ----------------
__device__ __align__(16) float g_sact[(size_t)NTOK * ISH];          // shared-expert SwiGLU act
__device__ __align__(16) float g_eact[(size_t)NTOK * TOPK * IDIM];  // expert SwiGLU act (row = entry)
__device__ int   g_cnt[NEXP];
__device__ int   g_list[NEXP * NTOK];
__device__ float g_topw[NTOK * TOPK];
__device__ float g_gatesc[NTOK];

// ---------------- helpers ----------------
__device__ __forceinline__ float tf(float x) {
    uint32_t r;
    asm("cvt.rna.tf32.f32 %0, %1;" : "=r"(r) : "f"(x));
    return __uint_as_float(r);
}
__device__ __forceinline__ float4 tf4(float4 v) {
    v.x = tf(v.x); v.y = tf(v.y); v.z = tf(v.z); v.w = tf(v.w);
    return v;
}
__device__ __forceinline__ void mma8(float* d, const uint32_t* a, const uint32_t* b) {
    asm volatile(
        "mma.sync.aligned.m16n8k8.row.col.f32.tf32.tf32.f32 "
        "{%0,%1,%2,%3}, {%4,%5,%6,%7}, {%8,%9}, {%0,%1,%2,%3};"
        : "+f"(d[0]), "+f"(d[1]), "+f"(d[2]), "+f"(d[3])
        : "r"(a[0]), "r"(a[1]), "r"(a[2]), "r"(a[3]), "r"(b[0]), "r"(b[1]));
}
__device__ __forceinline__ float silu_mul(float g, float u) {
    return g / (1.f + expf(-g)) * u;
}

// ---------------- setup ----------------
__global__ void setup_kernel(float* out, int out_size) {
    int t = threadIdx.x;
    if (t < NEXP) g_cnt[t] = 0;
    if (t == 0)
        for (int i = NTOK * HDIM; i < out_size; i++) out[i] = (float)NEXP;  // aux = E exactly
}

// ---------------- router (fp32 exact) ----------------
__global__ void router_kernel(const float* __restrict__ h,
                              const float* __restrict__ rw,
                              const float* __restrict__ egw) {
    int n = blockIdx.x, tid = threadIdx.x, lane = tid & 31, w = tid >> 5;
    __shared__ float hs[HDIM];
    __shared__ float logits[NEXP + 1];
    const float4* hp = (const float4*)(h + (size_t)n * HDIM);
    float4* hs4 = (float4*)hs;
    for (int i = tid; i < HDIM / 4; i += 128) hs4[i] = hp[i];
    __syncthreads();
    for (int e = w; e < NEXP + 1; e += 4) {
        const float* wr = (e < NEXP) ? (rw + (size_t)e * HDIM) : egw;
        float s = 0.f;
        for (int i = lane; i < HDIM; i += 32) s += hs[i] * wr[i];
        for (int o = 16; o > 0; o >>= 1) s += __shfl_down_sync(0xffffffffu, s, o);
        if (lane == 0) logits[e] = s;
    }
    __syncthreads();
    if (tid == 0) {
        float mx = -1e30f;
        for (int e = 0; e < NEXP; e++) mx = fmaxf(mx, logits[e]);
        float p[NEXP], den = 0.f;
        for (int e = 0; e < NEXP; e++) { p[e] = expf(logits[e] - mx); den += p[e]; }
        float inv = 1.f / den;
        for (int e = 0; e < NEXP; e++) p[e] *= inv;
        int sel[TOPK]; float sv[TOPK]; float ssum = 0.f;
        for (int k = 0; k < TOPK; k++) {
            int bi = 0; float bv = -1.f;
            for (int e = 0; e < NEXP; e++) if (p[e] > bv) { bv = p[e]; bi = e; }
            sel[k] = bi; sv[k] = bv; ssum += bv; p[bi] = -2.f;
        }
        float rinv = 1.f / ssum;
        for (int k = 0; k < TOPK; k++) {
            int entry = n * TOPK + k;
            g_topw[entry] = sv[k] * rinv;
            int pos = atomicAdd(&g_cnt[sel[k]], 1);
            g_list[sel[k] * NTOK + pos] = entry;
        }
        g_gatesc[n] = 1.f / (1.f + expf(-logits[NEXP]));
    }
}

// =====================================================================
// mma.sync tf32 GEMM kernels. NT: C[m,n] = dot(A[m,:K], B[n,:K]).
// Block 128x128, BK=32, 8 warps (2 along M x 4 along N), warp tile 64x32.
// SMEM tiles padded to 36 floats/row -> conflict-free fragment LDS.
// =====================================================================

// fragment loaders (A0/B0 point at the staged 128x32 tile)
#define LOAD_AFRAG(af, A0, mbase, ks)                                            \
    do {                                                                          \
        int _r = (mbase) + g, _k = (ks) * 8 + c;                                  \
        af[0] = __float_as_uint((A0)[_r * PAD + _k]);                             \
        af[1] = __float_as_uint((A0)[(_r + 8) * PAD + _k]);                       \
        af[2] = __float_as_uint((A0)[_r * PAD + _k + 4]);                         \
        af[3] = __float_as_uint((A0)[(_r + 8) * PAD + _k + 4]);                   \
    } while (0)
#define LOAD_BFRAG(bf, B0, nbase, ks)                                             \
    do {                                                                          \
        int _n = (nbase) + g, _k = (ks) * 8 + c;                                  \
        bf[0] = __float_as_uint((B0)[_n * PAD + _k]);                             \
        bf[1] = __float_as_uint((B0)[_n * PAD + _k + 4]);                         \
    } while (0)

// ---- shared gate/up (dual): g_sact = silu(h@Wg^T) * (h@Wu^T) ----
__global__ void __launch_bounds__(256) k_dual_shared(const float* __restrict__ A,
                                                     const float* __restrict__ Wg,
                                                     const float* __restrict__ Wu) {
    extern __shared__ float sm[];
    float* sA = sm;
    float* sG = sm + TILEF;
    float* sU = sm + 2 * TILEF;
    const int tid = threadIdx.x, lane = tid & 31, w = tid >> 5;
    const int wm = w & 1, wn = w >> 1, g = lane >> 2, c = lane & 3;
    const int row0 = blockIdx.y * 128, col0 = blockIdx.x * 128;
    const int lrow = tid >> 3, lc4 = (tid & 7) * 4;

    const float* Ab = A  + (size_t)(row0 + lrow) * HDIM + lc4;
    const float* Gb = Wg + (size_t)(col0 + lrow) * HDIM + lc4;
    const float* Ub = Wu + (size_t)(col0 + lrow) * HDIM + lc4;

    float4 ra[4], rg[4], ru[4];
#pragma unroll
    for (int s = 0; s < 4; s++) {
        ra[s] = *(const float4*)(Ab + (size_t)s * 32 * HDIM);
        rg[s] = *(const float4*)(Gb + (size_t)s * 32 * HDIM);
        ru[s] = *(const float4*)(Ub + (size_t)s * 32 * HDIM);
    }
    float accg[4][4][4] = {}, accu[4][4][4] = {};
    const int NCH = HDIM / 32;
    for (int ch = 0; ch < NCH; ch++) {
#pragma unroll
        for (int s = 0; s < 4; s++) {
            int ro = (lrow + 32 * s) * PAD + lc4;
            *(float4*)&sA[ro] = tf4(ra[s]);
            *(float4*)&sG[ro] = tf4(rg[s]);
            *(float4*)&sU[ro] = tf4(ru[s]);
        }
        __syncthreads();
        if (ch + 1 < NCH) {
            int k0 = (ch + 1) * 32;
#pragma unroll
            for (int s = 0; s < 4; s++) {
                ra[s] = *(const float4*)(Ab + (size_t)s * 32 * HDIM + k0);
                rg[s] = *(const float4*)(Gb + (size_t)s * 32 * HDIM + k0);
                ru[s] = *(const float4*)(Ub + (size_t)s * 32 * HDIM + k0);
            }
        }
#pragma unroll
        for (int ks = 0; ks < 4; ks++) {
            uint32_t af[4][4], bg[4][2], bu[4][2];
#pragma unroll
            for (int mi = 0; mi < 4; mi++) LOAD_AFRAG(af[mi], sA, wm * 64 + mi * 16, ks);
#pragma unroll
            for (int ni = 0; ni < 4; ni++) {
                LOAD_BFRAG(bg[ni], sG, wn * 32 + ni * 8, ks);
                LOAD_BFRAG(bu[ni], sU, wn * 32 + ni * 8, ks);
            }
#pragma unroll
            for (int mi = 0; mi < 4; mi++)
#pragma unroll
                for (int ni = 0; ni < 4; ni++) {
                    mma8(accg[mi][ni], af[mi], bg[ni]);
                    mma8(accu[mi][ni], af[mi], bu[ni]);
                }
        }
        __syncthreads();
    }
#pragma unroll
    for (int mi = 0; mi < 4; mi++) {
        int r = row0 + wm * 64 + mi * 16 + g;
#pragma unroll
        for (int ni = 0; ni < 4; ni++) {
            int cc = col0 + wn * 32 + ni * 8 + 2 * c;
            float2 o0, o1;
            o0.x = silu_mul(accg[mi][ni][0], accu[mi][ni][0]);
            o0.y = silu_mul(accg[mi][ni][1], accu[mi][ni][1]);
            o1.x = silu_mul(accg[mi][ni][2], accu[mi][ni][2]);
            o1.y = silu_mul(accg[mi][ni][3], accu[mi][ni][3]);
            *(float2*)&g_sact[(size_t)r * ISH + cc] = o0;
            *(float2*)&g_sact[(size_t)(r + 8) * ISH + cc] = o1;
        }
    }
}

// ---- shared down: out = gatesc * (g_sact @ sdw^T) ----
__global__ void __launch_bounds__(256) k_single_shared(const float* __restrict__ Wd,
                                                       float* __restrict__ out) {
    extern __shared__ float sm[];
    float* sA = sm;
    float* sB = sm + TILEF;
    const int tid = threadIdx.x, lane = tid & 31, w = tid >> 5;
    const int wm = w & 1, wn = w >> 1, g = lane >> 2, c = lane & 3;
    const int row0 = blockIdx.y * 128, col0 = blockIdx.x * 128;
    const int lrow = tid >> 3, lc4 = (tid & 7) * 4;

    const float* Ab = g_sact + (size_t)(row0 + lrow) * ISH + lc4;
    const float* Bb = Wd + (size_t)(col0 + lrow) * ISH + lc4;

    float4 ra[4], rb[4];
#pragma unroll
    for (int s = 0; s < 4; s++) {
        ra[s] = *(const float4*)(Ab + (size_t)s * 32 * ISH);
        rb[s] = *(const float4*)(Bb + (size_t)s * 32 * ISH);
    }
    float acc[4][4][4] = {};
    const int NCH = ISH / 32;
    for (int ch = 0; ch < NCH; ch++) {
#pragma unroll
        for (int s = 0; s < 4; s++) {
            int ro = (lrow + 32 * s) * PAD + lc4;
            *(float4*)&sA[ro] = tf4(ra[s]);
            *(float4*)&sB[ro] = tf4(rb[s]);
        }
        __syncthreads();
        if (ch + 1 < NCH) {
            int k0 = (ch + 1) * 32;
#pragma unroll
            for (int s = 0; s < 4; s++) {
                ra[s] = *(const float4*)(Ab + (size_t)s * 32 * ISH + k0);
                rb[s] = *(const float4*)(Bb + (size_t)s * 32 * ISH + k0);
            }
        }
#pragma unroll
        for (int ks = 0; ks < 4; ks++) {
            uint32_t af[4][4], bf[4][2];
#pragma unroll
            for (int mi = 0; mi < 4; mi++) LOAD_AFRAG(af[mi], sA, wm * 64 + mi * 16, ks);
#pragma unroll
            for (int ni = 0; ni < 4; ni++) LOAD_BFRAG(bf[ni], sB, wn * 32 + ni * 8, ks);
#pragma unroll
            for (int mi = 0; mi < 4; mi++)
#pragma unroll
                for (int ni = 0; ni < 4; ni++) mma8(acc[mi][ni], af[mi], bf[ni]);
        }
        __syncthreads();
    }
#pragma unroll
    for (int mi = 0; mi < 4; mi++) {
        int r = row0 + wm * 64 + mi * 16 + g;
        float s0 = g_gatesc[r], s1 = g_gatesc[r + 8];
#pragma unroll
        for (int ni = 0; ni < 4; ni++) {
            int cc = col0 + wn * 32 + ni * 8 + 2 * c;
            float2 o0 = {s0 * acc[mi][ni][0], s0 * acc[mi][ni][1]};
            float2 o1 = {s1 * acc[mi][ni][2], s1 * acc[mi][ni][3]};
            *(float2*)&out[(size_t)r * HDIM + cc] = o0;
            *(float2*)&out[(size_t)(r + 8) * HDIM + cc] = o1;
        }
    }
}

// ---- expert gate/up (dual, gathered A rows): g_eact[entry] = silu(g)*u ----
__global__ void __launch_bounds__(256) k_dual_expert(const float* __restrict__ h,
                                                     const float* __restrict__ gup) {
    const int e = blockIdx.z;
    const int cnt = g_cnt[e];
    const int m0 = blockIdx.y * 128;
    if (m0 >= cnt) return;

    extern __shared__ float sm[];
    float* sA = sm;
    float* sG = sm + TILEF;
    float* sU = sm + 2 * TILEF;
    __shared__ const float* rp[128];
    __shared__ int ents[128];
    const int tid = threadIdx.x, lane = tid & 31, w = tid >> 5;
    const int wm = w & 1, wn = w >> 1, g = lane >> 2, c = lane & 3;
    const int col0 = blockIdx.x * 128;
    const int lrow = tid >> 3, lc4 = (tid & 7) * 4;

    if (tid < 128) {
        int r = min(m0 + tid, cnt - 1);
        int entry = g_list[e * NTOK + r];
        rp[tid] = h + (size_t)(entry >> 2) * HDIM;
        ents[tid] = entry;
    }
    __syncthreads();

    const float* Gb = gup + ((size_t)e * 2 * IDIM + col0 + lrow) * HDIM + lc4;
    const float* Ub = gup + ((size_t)e * 2 * IDIM + IDIM + col0 + lrow) * HDIM + lc4;

    float4 ra[4], rg[4], ru[4];
#pragma unroll
    for (int s = 0; s < 4; s++) {
        ra[s] = *(const float4*)(rp[lrow + 32 * s] + lc4);
        rg[s] = *(const float4*)(Gb + (size_t)s * 32 * HDIM);
        ru[s] = *(const float4*)(Ub + (size_t)s * 32 * HDIM);
    }
    float accg[4][4][4] = {}, accu[4][4][4] = {};
    const int NCH = HDIM / 32;
    for (int ch = 0; ch < NCH; ch++) {
#pragma unroll
        for (int s = 0; s < 4; s++) {
            int ro = (lrow + 32 * s) * PAD + lc4;
            *(float4*)&sA[ro] = tf4(ra[s]);
            *(float4*)&sG[ro] = tf4(rg[s]);
            *(float4*)&sU[ro] = tf4(ru[s]);
        }
        __syncthreads();
        if (ch + 1 < NCH) {
            int k0 = (ch + 1) * 32;
#pragma unroll
            for (int s = 0; s < 4; s++) {
                ra[s] = *(const float4*)(rp[lrow + 32 * s] + lc4 + k0);
                rg[s] = *(const float4*)(Gb + (size_t)s * 32 * HDIM + k0);
                ru[s] = *(const float4*)(Ub + (size_t)s * 32 * HDIM + k0);
            }
        }
#pragma unroll
        for (int ks = 0; ks < 4; ks++) {
            uint32_t af[4][4], bg[4][2], bu[4][2];
#pragma unroll
            for (int mi = 0; mi < 4; mi++) LOAD_AFRAG(af[mi], sA, wm * 64 + mi * 16, ks);
#pragma unroll
            for (int ni = 0; ni < 4; ni++) {
                LOAD_BFRAG(bg[ni], sG, wn * 32 + ni * 8, ks);
                LOAD_BFRAG(bu[ni], sU, wn * 32 + ni * 8, ks);
            }
#pragma unroll
            for (int mi = 0; mi < 4; mi++)
#pragma unroll
                for (int ni = 0; ni < 4; ni++) {
                    mma8(accg[mi][ni], af[mi], bg[ni]);
                    mma8(accu[mi][ni], af[mi], bu[ni]);
                }
        }
        __syncthreads();
    }
#pragma unroll
    for (int mi = 0; mi < 4; mi++) {
        int rl0 = wm * 64 + mi * 16 + g;
        bool v0 = (m0 + rl0) < cnt, v1 = (m0 + rl0 + 8) < cnt;
        int e0 = ents[rl0], e1 = ents[rl0 + 8];
#pragma unroll
        for (int ni = 0; ni < 4; ni++) {
            int cc = col0 + wn * 32 + ni * 8 + 2 * c;
            if (v0) {
                float2 o = {silu_mul(accg[mi][ni][0], accu[mi][ni][0]),
                            silu_mul(accg[mi][ni][1], accu[mi][ni][1])};
                *(float2*)&g_eact[(size_t)e0 * IDIM + cc] = o;
            }
            if (v1) {
                float2 o = {silu_mul(accg[mi][ni][2], accu[mi][ni][2]),
                            silu_mul(accg[mi][ni][3], accu[mi][ni][3])};
                *(float2*)&g_eact[(size_t)e1 * IDIM + cc] = o;
            }
        }
    }
}

// ---- expert down (gathered A, atomic scatter): out += w * (g_eact @ dwn^T) ----
__global__ void __launch_bounds__(256) k_single_expert(const float* __restrict__ dwn,
                                                       float* __restrict__ out) {
    const int e = blockIdx.z;
    const int cnt = g_cnt[e];
    const int m0 = blockIdx.y * 128;
    if (m0 >= cnt) return;

    extern __shared__ float sm[];
    float* sA = sm;
    float* sB = sm + TILEF;
    __shared__ const float* rp[128];
    __shared__ int ents[128];
    const int tid = threadIdx.x, lane = tid & 31, w = tid >> 5;
    const int wm = w & 1, wn = w >> 1, g = lane >> 2, c = lane & 3;
    const int col0 = blockIdx.x * 128;
    const int lrow = tid >> 3, lc4 = (tid & 7) * 4;

    if (tid < 128) {
        int r = min(m0 + tid, cnt - 1);
        int entry = g_list[e * NTOK + r];
        rp[tid] = g_eact + (size_t)entry * IDIM;
        ents[tid] = entry;
    }
    __syncthreads();

    const float* Bb = dwn + ((size_t)e * HDIM + col0 + lrow) * IDIM + lc4;

    float4 ra[4], rb[4];
#pragma unroll
    for (int s = 0; s < 4; s++) {
        ra[s] = *(const float4*)(rp[lrow + 32 * s] + lc4);
        rb[s] = *(const float4*)(Bb + (size_t)s * 32 * IDIM);
    }
    float acc[4][4][4] = {};
    const int NCH = IDIM / 32;
    for (int ch = 0; ch < NCH; ch++) {
#pragma unroll
        for (int s = 0; s < 4; s++) {
            int ro = (lrow + 32 * s) * PAD + lc4;
            *(float4*)&sA[ro] = tf4(ra[s]);
            *(float4*)&sB[ro] = tf4(rb[s]);
        }
        __syncthreads();
        if (ch + 1 < NCH) {
            int k0 = (ch + 1) * 32;
#pragma unroll
            for (int s = 0; s < 4; s++) {
                ra[s] = *(const float4*)(rp[lrow + 32 * s] + lc4 + k0);
                rb[s] = *(const float4*)(Bb + (size_t)s * 32 * IDIM + k0);
            }
        }
#pragma unroll
        for (int ks = 0; ks < 4; ks++) {
            uint32_t af[4][4], bf[4][2];
#pragma unroll
            for (int mi = 0; mi < 4; mi++) LOAD_AFRAG(af[mi], sA, wm * 64 + mi * 16, ks);
#pragma unroll
            for (int ni = 0; ni < 4; ni++) LOAD_BFRAG(bf[ni], sB, wn * 32 + ni * 8, ks);
#pragma unroll
            for (int mi = 0; mi < 4; mi++)
#pragma unroll
                for (int ni = 0; ni < 4; ni++) mma8(acc[mi][ni], af[mi], bf[ni]);
        }
        __syncthreads();
    }
#pragma unroll
    for (int mi = 0; mi < 4; mi++) {
        int rl0 = wm * 64 + mi * 16 + g;
        bool v0 = (m0 + rl0) < cnt, v1 = (m0 + rl0 + 8) < cnt;
        int e0 = ents[rl0], e1 = ents[rl0 + 8];
        float w0 = v0 ? g_topw[e0] : 0.f;
        float w1 = v1 ? g_topw[e1] : 0.f;
        float* d0 = out + (size_t)(e0 >> 2) * HDIM;
        float* d1 = out + (size_t)(e1 >> 2) * HDIM;
#pragma unroll
        for (int ni = 0; ni < 4; ni++) {
            int cc = col0 + wn * 32 + ni * 8 + 2 * c;
            if (v0) {
                atomicAdd(d0 + cc, w0 * acc[mi][ni][0]);
                atomicAdd(d0 + cc + 1, w0 * acc[mi][ni][1]);
            }
            if (v1) {
                atomicAdd(d1 + cc, w1 * acc[mi][ni][2]);
                atomicAdd(d1 + cc + 1, w1 * acc[mi][ni][3]);
            }
        }
    }
}

// ---------------------------------------------------------------------------
extern "C" void kernel_launch(void* const* d_in, const int* in_sizes, int n_in,
                              void* d_out, int out_size) {
    const float* h    = (const float*)d_in[0];
    const float* rw   = (const float*)d_in[1];
    const float* gup  = (const float*)d_in[2];
    const float* dwn  = (const float*)d_in[3];
    const float* sgw  = (const float*)d_in[4];
    const float* suw  = (const float*)d_in[5];
    const float* sdw  = (const float*)d_in[6];
    const float* segw = (const float*)d_in[7];
    float* out = (float*)d_out;

    const int DUAL_SMEM = 3 * TILEF * 4;    // 55296
    const int SINGLE_SMEM = 2 * TILEF * 4;  // 36864
    static bool attr_done = false;
    if (!attr_done) {
        cudaFuncSetAttribute(k_dual_shared, cudaFuncAttributeMaxDynamicSharedMemorySize, DUAL_SMEM);
        cudaFuncSetAttribute(k_dual_expert, cudaFuncAttributeMaxDynamicSharedMemorySize, DUAL_SMEM);
        attr_done = true;
    }

    setup_kernel<<<1, 32>>>(out, out_size);
    router_kernel<<<NTOK, 128>>>(h, rw, segw);
    k_dual_shared<<<dim3(ISH / 128, NTOK / 128), 256, DUAL_SMEM>>>(h, sgw, suw);
    k_dual_expert<<<dim3(IDIM / 128, NTOK / 128, NEXP), 256, DUAL_SMEM>>>(h, gup);
    k_single_shared<<<dim3(HDIM / 128, NTOK / 128), 256, SINGLE_SMEM>>>(sdw, out);
    k_single_expert<<<dim3(HDIM / 128, NTOK / 128, NEXP), 256, SINGLE_SMEM>>>(dwn, out);
}

// round 4
// speedup vs baseline: 4.1055x; 1.6866x over previous
#include <cuda_runtime.h>
#include <cstdint>
#include <math.h>

#define NTOK 4096
#define HDIM 1024
#define NEXP 16
#define IDIM 512
#define ISH  2048
#define TOPK 4

#define PAD     36
#define SROWS   256                    // rows per pipeline stage (A:128 + B/G/U:128)
#define SSTRIDE (SROWS * PAD)          // floats per stage
#define PIPE_SMEM (2 * SSTRIDE * 4)    // 73728 bytes

// ---------------- scratch (device globals; no allocation APIs) ----------------
__device__ __align__(16) float g_sact[(size_t)NTOK * ISH];
__device__ __align__(16) float g_eact[(size_t)NTOK * TOPK * IDIM];
__device__ int   g_cnt[NEXP];
__device__ int   g_list[NEXP * NTOK];
__device__ float g_topw[NTOK * TOPK];
__device__ float g_gatesc[NTOK];

// ---------------- helpers ----------------
__device__ __forceinline__ uint32_t smem_u32(const void* p) {
    uint32_t a;
    asm("{ .reg .u64 t; cvta.to.shared.u64 t, %1; cvt.u32.u64 %0, t; }" : "=r"(a) : "l"(p));
    return a;
}
__device__ __forceinline__ uint32_t tfu(float x) {
    uint32_t r;
    asm("cvt.rna.tf32.f32 %0, %1;" : "=r"(r) : "f"(x));
    return r;
}
__device__ __forceinline__ void mma8(float* d, const uint32_t* a, const uint32_t* b) {
    asm volatile(
        "mma.sync.aligned.m16n8k8.row.col.f32.tf32.tf32.f32 "
        "{%0,%1,%2,%3}, {%4,%5,%6,%7}, {%8,%9}, {%0,%1,%2,%3};"
        : "+f"(d[0]), "+f"(d[1]), "+f"(d[2]), "+f"(d[3])
        : "r"(a[0]), "r"(a[1]), "r"(a[2]), "r"(a[3]), "r"(b[0]), "r"(b[1]));
}
__device__ __forceinline__ float silu_mul(float g, float u) {
    return g / (1.f + expf(-g)) * u;
}
__device__ __forceinline__ void cp16(uint32_t dst, const float* src) {
    asm volatile("cp.async.cg.shared.global [%0], [%1], 16;" :: "r"(dst), "l"(src));
}
#define CP_COMMIT() asm volatile("cp.async.commit_group;" ::: "memory")
#define CP_WAIT1()  asm volatile("cp.async.wait_group 1;" ::: "memory")

// fragment loaders from padded SMEM (float view), with tf32 rounding
#define LOAD_AFRAG(af, smf, toff, mbase, ks)                                   \
    do {                                                                        \
        int _r = (mbase) + g, _k = (ks) * 8 + c;                                \
        af[0] = tfu((smf)[(toff) + _r * PAD + _k]);                             \
        af[1] = tfu((smf)[(toff) + (_r + 8) * PAD + _k]);                       \
        af[2] = tfu((smf)[(toff) + _r * PAD + _k + 4]);                         \
        af[3] = tfu((smf)[(toff) + (_r + 8) * PAD + _k + 4]);                   \
    } while (0)
#define LOAD_BFRAG(bf, smf, toff, nbase, ks)                                   \
    do {                                                                        \
        int _n = (nbase) + g, _k = (ks) * 8 + c;                                \
        bf[0] = tfu((smf)[(toff) + _n * PAD + _k]);                             \
        bf[1] = tfu((smf)[(toff) + _n * PAD + _k + 4]);                         \
    } while (0)

// ---------------- setup ----------------
__global__ void setup_kernel(float* out, int out_size) {
    int t = threadIdx.x;
    if (t < NEXP) g_cnt[t] = 0;
    if (t == 0)
        for (int i = NTOK * HDIM; i < out_size; i++) out[i] = (float)NEXP;  // aux = E exactly
}

// ---------------- router (fp32 exact) ----------------
__global__ void router_kernel(const float* __restrict__ h,
                              const float* __restrict__ rw,
                              const float* __restrict__ egw) {
    int n = blockIdx.x, tid = threadIdx.x, lane = tid & 31, w = tid >> 5;
    __shared__ float hs[HDIM];
    __shared__ float logits[NEXP + 1];
    const float4* hp = (const float4*)(h + (size_t)n * HDIM);
    float4* hs4 = (float4*)hs;
    for (int i = tid; i < HDIM / 4; i += 128) hs4[i] = hp[i];
    __syncthreads();
    for (int e = w; e < NEXP + 1; e += 4) {
        const float* wr = (e < NEXP) ? (rw + (size_t)e * HDIM) : egw;
        float s = 0.f;
        for (int i = lane; i < HDIM; i += 32) s += hs[i] * wr[i];
        for (int o = 16; o > 0; o >>= 1) s += __shfl_down_sync(0xffffffffu, s, o);
        if (lane == 0) logits[e] = s;
    }
    __syncthreads();
    if (tid == 0) {
        float mx = -1e30f;
        for (int e = 0; e < NEXP; e++) mx = fmaxf(mx, logits[e]);
        float p[NEXP], den = 0.f;
        for (int e = 0; e < NEXP; e++) { p[e] = expf(logits[e] - mx); den += p[e]; }
        float inv = 1.f / den;
        for (int e = 0; e < NEXP; e++) p[e] *= inv;
        int sel[TOPK]; float sv[TOPK]; float ssum = 0.f;
        for (int k = 0; k < TOPK; k++) {
            int bi = 0; float bv = -1.f;
            for (int e = 0; e < NEXP; e++) if (p[e] > bv) { bv = p[e]; bi = e; }
            sel[k] = bi; sv[k] = bv; ssum += bv; p[bi] = -2.f;
        }
        float rinv = 1.f / ssum;
        for (int k = 0; k < TOPK; k++) {
            int entry = n * TOPK + k;
            g_topw[entry] = sv[k] * rinv;
            int pos = atomicAdd(&g_cnt[sel[k]], 1);
            g_list[sel[k] * NTOK + pos] = entry;
        }
        g_gatesc[n] = 1.f / (1.f + expf(-logits[NEXP]));
    }
}

// =====================================================================
// cp.async double-buffered tf32 mma.sync GEMMs. NT: C[m,n]=dot(A[m,:],B[n,:]).
// DUAL:   block 128(M) x 64(I-cols), 8 warps 4x2, warp tile 32x32 per output.
// SINGLE: block 128(M) x 128(N),     8 warps 2x4, warp tile 64x32.
// Stage layout (rows of PAD=36 floats): [0,128) A, [128,256) B/G+U.
// =====================================================================

// ---- shared gate/up (dual): g_sact = silu(h@Wg^T) * (h@Wu^T) ----
__global__ void __launch_bounds__(256, 2) k_dual_shared(const float* __restrict__ A,
                                                        const float* __restrict__ Wg,
                                                        const float* __restrict__ Wu) {
    extern __shared__ float smf[];
    uint32_t sb = smem_u32(smf);
    const int tid = threadIdx.x, lane = tid & 31, w = tid >> 5;
    const int wm = w & 3, wn = w >> 2, g = lane >> 2, c = lane & 3;
    const int row0 = blockIdx.y * 128, col0 = blockIdx.x * 64;
    const int lr = tid >> 3, c4 = (tid & 7) * 4;

    const float* Ab = A  + (size_t)(row0 + lr) * HDIM + c4;
    const float* Gb = Wg + (size_t)(col0 + lr) * HDIM + c4;
    const float* Ub = Wu + (size_t)(col0 + lr) * HDIM + c4;

#define DS_LOAD(stage, k0)                                                        \
    do {                                                                           \
        uint32_t so = sb + (uint32_t)(stage) * SSTRIDE * 4;                        \
        _Pragma("unroll") for (int s = 0; s < 4; s++)                              \
            cp16(so + (uint32_t)((lr + 32 * s) * PAD + c4) * 4,                    \
                 Ab + (size_t)(32 * s) * HDIM + (k0));                             \
        _Pragma("unroll") for (int s = 0; s < 2; s++) {                            \
            cp16(so + (uint32_t)((128 + lr + 32 * s) * PAD + c4) * 4,              \
                 Gb + (size_t)(32 * s) * HDIM + (k0));                             \
            cp16(so + (uint32_t)((192 + lr + 32 * s) * PAD + c4) * 4,              \
                 Ub + (size_t)(32 * s) * HDIM + (k0));                             \
        }                                                                          \
    } while (0)

    DS_LOAD(0, 0); CP_COMMIT();
    DS_LOAD(1, 32); CP_COMMIT();

    float accg[2][4][4] = {}, accu[2][4][4] = {};
    const int NIT = HDIM / 32;
    for (int it = 0; it < NIT; it++) {
        int b = it & 1;
        int toff = b * SSTRIDE;
        CP_WAIT1();
        __syncthreads();
#pragma unroll
        for (int ks = 0; ks < 4; ks++) {
            uint32_t af[2][4], bg[4][2], bu[4][2];
#pragma unroll
            for (int mi = 0; mi < 2; mi++) LOAD_AFRAG(af[mi], smf, toff, wm * 32 + mi * 16, ks);
#pragma unroll
            for (int ni = 0; ni < 4; ni++) {
                LOAD_BFRAG(bg[ni], smf, toff + 128 * PAD, wn * 32 + ni * 8, ks);
                LOAD_BFRAG(bu[ni], smf, toff + 192 * PAD, wn * 32 + ni * 8, ks);
            }
#pragma unroll
            for (int mi = 0; mi < 2; mi++)
#pragma unroll
                for (int ni = 0; ni < 4; ni++) {
                    mma8(accg[mi][ni], af[mi], bg[ni]);
                    mma8(accu[mi][ni], af[mi], bu[ni]);
                }
        }
        __syncthreads();
        if (it + 2 < NIT) DS_LOAD(b, (it + 2) * 32);
        CP_COMMIT();
    }
#undef DS_LOAD
#pragma unroll
    for (int mi = 0; mi < 2; mi++) {
        int r = row0 + wm * 32 + mi * 16 + g;
#pragma unroll
        for (int ni = 0; ni < 4; ni++) {
            int cc = col0 + wn * 32 + ni * 8 + 2 * c;
            float2 o0, o1;
            o0.x = silu_mul(accg[mi][ni][0], accu[mi][ni][0]);
            o0.y = silu_mul(accg[mi][ni][1], accu[mi][ni][1]);
            o1.x = silu_mul(accg[mi][ni][2], accu[mi][ni][2]);
            o1.y = silu_mul(accg[mi][ni][3], accu[mi][ni][3]);
            *(float2*)&g_sact[(size_t)r * ISH + cc] = o0;
            *(float2*)&g_sact[(size_t)(r + 8) * ISH + cc] = o1;
        }
    }
}

// ---- shared down: out = gatesc * (g_sact @ sdw^T) ----
__global__ void __launch_bounds__(256, 2) k_single_shared(const float* __restrict__ Wd,
                                                          float* __restrict__ out) {
    extern __shared__ float smf[];
    uint32_t sb = smem_u32(smf);
    const int tid = threadIdx.x, lane = tid & 31, w = tid >> 5;
    const int wm = w & 1, wn = w >> 1, g = lane >> 2, c = lane & 3;
    const int row0 = blockIdx.y * 128, col0 = blockIdx.x * 128;
    const int lr = tid >> 3, c4 = (tid & 7) * 4;

    const float* Ab = g_sact + (size_t)(row0 + lr) * ISH + c4;
    const float* Bb = Wd + (size_t)(col0 + lr) * ISH + c4;

#define SS_LOAD(stage, k0)                                                        \
    do {                                                                           \
        uint32_t so = sb + (uint32_t)(stage) * SSTRIDE * 4;                        \
        _Pragma("unroll") for (int s = 0; s < 4; s++) {                            \
            cp16(so + (uint32_t)((lr + 32 * s) * PAD + c4) * 4,                    \
                 Ab + (size_t)(32 * s) * ISH + (k0));                              \
            cp16(so + (uint32_t)((128 + lr + 32 * s) * PAD + c4) * 4,              \
                 Bb + (size_t)(32 * s) * ISH + (k0));                              \
        }                                                                          \
    } while (0)

    SS_LOAD(0, 0); CP_COMMIT();
    SS_LOAD(1, 32); CP_COMMIT();

    float acc[4][4][4] = {};
    const int NIT = ISH / 32;
    for (int it = 0; it < NIT; it++) {
        int b = it & 1;
        int toff = b * SSTRIDE;
        CP_WAIT1();
        __syncthreads();
#pragma unroll
        for (int ks = 0; ks < 4; ks++) {
            uint32_t af[4][4], bf[4][2];
#pragma unroll
            for (int mi = 0; mi < 4; mi++) LOAD_AFRAG(af[mi], smf, toff, wm * 64 + mi * 16, ks);
#pragma unroll
            for (int ni = 0; ni < 4; ni++) LOAD_BFRAG(bf[ni], smf, toff + 128 * PAD, wn * 32 + ni * 8, ks);
#pragma unroll
            for (int mi = 0; mi < 4; mi++)
#pragma unroll
                for (int ni = 0; ni < 4; ni++) mma8(acc[mi][ni], af[mi], bf[ni]);
        }
        __syncthreads();
        if (it + 2 < NIT) SS_LOAD(b, (it + 2) * 32);
        CP_COMMIT();
    }
#undef SS_LOAD
#pragma unroll
    for (int mi = 0; mi < 4; mi++) {
        int r = row0 + wm * 64 + mi * 16 + g;
        float s0 = g_gatesc[r], s1 = g_gatesc[r + 8];
#pragma unroll
        for (int ni = 0; ni < 4; ni++) {
            int cc = col0 + wn * 32 + ni * 8 + 2 * c;
            float2 o0 = {s0 * acc[mi][ni][0], s0 * acc[mi][ni][1]};
            float2 o1 = {s1 * acc[mi][ni][2], s1 * acc[mi][ni][3]};
            *(float2*)&out[(size_t)r * HDIM + cc] = o0;
            *(float2*)&out[(size_t)(r + 8) * HDIM + cc] = o1;
        }
    }
}

// ---- expert gate/up (dual, gathered A rows): g_eact[entry] = silu(g)*u ----
__global__ void __launch_bounds__(256, 2) k_dual_expert(const float* __restrict__ h,
                                                        const float* __restrict__ gup) {
    const int e = blockIdx.z;
    const int cnt = g_cnt[e];
    const int m0 = blockIdx.y * 128;
    if (m0 >= cnt) return;

    extern __shared__ float smf[];
    uint32_t sb = smem_u32(smf);
    __shared__ const float* rp[128];
    __shared__ int ents[128];
    const int tid = threadIdx.x, lane = tid & 31, w = tid >> 5;
    const int wm = w & 3, wn = w >> 2, g = lane >> 2, c = lane & 3;
    const int col0 = blockIdx.x * 64;
    const int lr = tid >> 3, c4 = (tid & 7) * 4;

    if (tid < 128) {
        int r = min(m0 + tid, cnt - 1);
        int entry = g_list[e * NTOK + r];
        rp[tid] = h + (size_t)(entry >> 2) * HDIM;
        ents[tid] = entry;
    }
    __syncthreads();

    const float* Ar[4];
#pragma unroll
    for (int s = 0; s < 4; s++) Ar[s] = rp[lr + 32 * s] + c4;
    const float* Gb = gup + ((size_t)e * 2 * IDIM + col0 + lr) * HDIM + c4;
    const float* Ub = gup + ((size_t)e * 2 * IDIM + IDIM + col0 + lr) * HDIM + c4;

#define DE_LOAD(stage, k0)                                                        \
    do {                                                                           \
        uint32_t so = sb + (uint32_t)(stage) * SSTRIDE * 4;                        \
        _Pragma("unroll") for (int s = 0; s < 4; s++)                              \
            cp16(so + (uint32_t)((lr + 32 * s) * PAD + c4) * 4, Ar[s] + (k0));     \
        _Pragma("unroll") for (int s = 0; s < 2; s++) {                            \
            cp16(so + (uint32_t)((128 + lr + 32 * s) * PAD + c4) * 4,              \
                 Gb + (size_t)(32 * s) * HDIM + (k0));                             \
            cp16(so + (uint32_t)((192 + lr + 32 * s) * PAD + c4) * 4,              \
                 Ub + (size_t)(32 * s) * HDIM + (k0));                             \
        }                                                                          \
    } while (0)

    DE_LOAD(0, 0); CP_COMMIT();
    DE_LOAD(1, 32); CP_COMMIT();

    float accg[2][4][4] = {}, accu[2][4][4] = {};
    const int NIT = HDIM / 32;
    for (int it = 0; it < NIT; it++) {
        int b = it & 1;
        int toff = b * SSTRIDE;
        CP_WAIT1();
        __syncthreads();
#pragma unroll
        for (int ks = 0; ks < 4; ks++) {
            uint32_t af[2][4], bg[4][2], bu[4][2];
#pragma unroll
            for (int mi = 0; mi < 2; mi++) LOAD_AFRAG(af[mi], smf, toff, wm * 32 + mi * 16, ks);
#pragma unroll
            for (int ni = 0; ni < 4; ni++) {
                LOAD_BFRAG(bg[ni], smf, toff + 128 * PAD, wn * 32 + ni * 8, ks);
                LOAD_BFRAG(bu[ni], smf, toff + 192 * PAD, wn * 32 + ni * 8, ks);
            }
#pragma unroll
            for (int mi = 0; mi < 2; mi++)
#pragma unroll
                for (int ni = 0; ni < 4; ni++) {
                    mma8(accg[mi][ni], af[mi], bg[ni]);
                    mma8(accu[mi][ni], af[mi], bu[ni]);
                }
        }
        __syncthreads();
        if (it + 2 < NIT) DE_LOAD(b, (it + 2) * 32);
        CP_COMMIT();
    }
#undef DE_LOAD
#pragma unroll
    for (int mi = 0; mi < 2; mi++) {
        int rl0 = wm * 32 + mi * 16 + g;
        bool v0 = (m0 + rl0) < cnt, v1 = (m0 + rl0 + 8) < cnt;
        int e0 = ents[rl0], e1 = ents[rl0 + 8];
#pragma unroll
        for (int ni = 0; ni < 4; ni++) {
            int cc = col0 + wn * 32 + ni * 8 + 2 * c;
            if (v0) {
                float2 o = {silu_mul(accg[mi][ni][0], accu[mi][ni][0]),
                            silu_mul(accg[mi][ni][1], accu[mi][ni][1])};
                *(float2*)&g_eact[(size_t)e0 * IDIM + cc] = o;
            }
            if (v1) {
                float2 o = {silu_mul(accg[mi][ni][2], accu[mi][ni][2]),
                            silu_mul(accg[mi][ni][3], accu[mi][ni][3])};
                *(float2*)&g_eact[(size_t)e1 * IDIM + cc] = o;
            }
        }
    }
}

// ---- expert down (gathered A, atomic scatter): out += w * (g_eact @ dwn^T) ----
__global__ void __launch_bounds__(256, 2) k_single_expert(const float* __restrict__ dwn,
                                                          float* __restrict__ out) {
    const int e = blockIdx.z;
    const int cnt = g_cnt[e];
    const int m0 = blockIdx.y * 128;
    if (m0 >= cnt) return;

    extern __shared__ float smf[];
    uint32_t sb = smem_u32(smf);
    __shared__ const float* rp[128];
    __shared__ int ents[128];
    const int tid = threadIdx.x, lane = tid & 31, w = tid >> 5;
    const int wm = w & 1, wn = w >> 1, g = lane >> 2, c = lane & 3;
    const int col0 = blockIdx.x * 128;
    const int lr = tid >> 3, c4 = (tid & 7) * 4;

    if (tid < 128) {
        int r = min(m0 + tid, cnt - 1);
        int entry = g_list[e * NTOK + r];
        rp[tid] = g_eact + (size_t)entry * IDIM;
        ents[tid] = entry;
    }
    __syncthreads();

    const float* Ar[4];
#pragma unroll
    for (int s = 0; s < 4; s++) Ar[s] = rp[lr + 32 * s] + c4;
    const float* Bb = dwn + ((size_t)e * HDIM + col0 + lr) * IDIM + c4;

#define SE_LOAD(stage, k0)                                                        \
    do {                                                                           \
        uint32_t so = sb + (uint32_t)(stage) * SSTRIDE * 4;                        \
        _Pragma("unroll") for (int s = 0; s < 4; s++) {                            \
            cp16(so + (uint32_t)((lr + 32 * s) * PAD + c4) * 4, Ar[s] + (k0));     \
            cp16(so + (uint32_t)((128 + lr + 32 * s) * PAD + c4) * 4,              \
                 Bb + (size_t)(32 * s) * IDIM + (k0));                             \
        }                                                                          \
    } while (0)

    SE_LOAD(0, 0); CP_COMMIT();
    SE_LOAD(1, 32); CP_COMMIT();

    float acc[4][4][4] = {};
    const int NIT = IDIM / 32;
    for (int it = 0; it < NIT; it++) {
        int b = it & 1;
        int toff = b * SSTRIDE;
        CP_WAIT1();
        __syncthreads();
#pragma unroll
        for (int ks = 0; ks < 4; ks++) {
            uint32_t af[4][4], bf[4][2];
#pragma unroll
            for (int mi = 0; mi < 4; mi++) LOAD_AFRAG(af[mi], smf, toff, wm * 64 + mi * 16, ks);
#pragma unroll
            for (int ni = 0; ni < 4; ni++) LOAD_BFRAG(bf[ni], smf, toff + 128 * PAD, wn * 32 + ni * 8, ks);
#pragma unroll
            for (int mi = 0; mi < 4; mi++)
#pragma unroll
                for (int ni = 0; ni < 4; ni++) mma8(acc[mi][ni], af[mi], bf[ni]);
        }
        __syncthreads();
        if (it + 2 < NIT) SE_LOAD(b, (it + 2) * 32);
        CP_COMMIT();
    }
#undef SE_LOAD
#pragma unroll
    for (int mi = 0; mi < 4; mi++) {
        int rl0 = wm * 64 + mi * 16 + g;
        bool v0 = (m0 + rl0) < cnt, v1 = (m0 + rl0 + 8) < cnt;
        int e0 = ents[rl0], e1 = ents[rl0 + 8];
        float w0 = v0 ? g_topw[e0] : 0.f;
        float w1 = v1 ? g_topw[e1] : 0.f;
        float* d0 = out + (size_t)(e0 >> 2) * HDIM;
        float* d1 = out + (size_t)(e1 >> 2) * HDIM;
#pragma unroll
        for (int ni = 0; ni < 4; ni++) {
            int cc = col0 + wn * 32 + ni * 8 + 2 * c;
            if (v0) {
                atomicAdd(d0 + cc, w0 * acc[mi][ni][0]);
                atomicAdd(d0 + cc + 1, w0 * acc[mi][ni][1]);
            }
            if (v1) {
                atomicAdd(d1 + cc, w1 * acc[mi][ni][2]);
                atomicAdd(d1 + cc + 1, w1 * acc[mi][ni][3]);
            }
        }
    }
}

// ---------------------------------------------------------------------------
extern "C" void kernel_launch(void* const* d_in, const int* in_sizes, int n_in,
                              void* d_out, int out_size) {
    const float* h    = (const float*)d_in[0];
    const float* rw   = (const float*)d_in[1];
    const float* gup  = (const float*)d_in[2];
    const float* dwn  = (const float*)d_in[3];
    const float* sgw  = (const float*)d_in[4];
    const float* suw  = (const float*)d_in[5];
    const float* sdw  = (const float*)d_in[6];
    const float* segw = (const float*)d_in[7];
    float* out = (float*)d_out;

    cudaFuncSetAttribute(k_dual_shared,   cudaFuncAttributeMaxDynamicSharedMemorySize, PIPE_SMEM);
    cudaFuncSetAttribute(k_dual_expert,   cudaFuncAttributeMaxDynamicSharedMemorySize, PIPE_SMEM);
    cudaFuncSetAttribute(k_single_shared, cudaFuncAttributeMaxDynamicSharedMemorySize, PIPE_SMEM);
    cudaFuncSetAttribute(k_single_expert, cudaFuncAttributeMaxDynamicSharedMemorySize, PIPE_SMEM);

    setup_kernel<<<1, 32>>>(out, out_size);
    router_kernel<<<NTOK, 128>>>(h, rw, segw);
    k_dual_shared<<<dim3(ISH / 64, NTOK / 128), 256, PIPE_SMEM>>>(h, sgw, suw);
    k_dual_expert<<<dim3(IDIM / 64, NTOK / 128, NEXP), 256, PIPE_SMEM>>>(h, gup);
    k_single_shared<<<dim3(HDIM / 128, NTOK / 128), 256, PIPE_SMEM>>>(sdw, out);
    k_single_expert<<<dim3(HDIM / 128, NTOK / 128, NEXP), 256, PIPE_SMEM>>>(dwn, out);
}

// round 5
// speedup vs baseline: 5.0722x; 1.2355x over previous
#include <cuda_runtime.h>
#include <cuda_fp16.h>
#include <cstdint>
#include <math.h>

#define NTOK 4096
#define HDIM 1024
#define NEXP 16
#define IDIM 512
#define ISH  2048
#define TOPK 4

#define RS        40                       // halves per smem row stride (80 bytes)
#define STAGE_B   (256 * RS * 2)           // 20480 bytes per stage (256 rows)
#define NSTAGE    4
#define GEMM_SMEM (NSTAGE * STAGE_B)       // 81920 bytes

// ---------------- fp16 operand copies + scratch (device globals) ----------------
__device__ __align__(16) __half g_h16[(size_t)NTOK * HDIM];
__device__ __align__(16) __half g_gup16[(size_t)NEXP * 2 * IDIM * HDIM];
__device__ __align__(16) __half g_dwn16[(size_t)NEXP * HDIM * IDIM];
__device__ __align__(16) __half g_sgw16[(size_t)ISH * HDIM];
__device__ __align__(16) __half g_suw16[(size_t)ISH * HDIM];
__device__ __align__(16) __half g_sdw16[(size_t)HDIM * ISH];
__device__ __align__(16) __half g_sact16[(size_t)NTOK * ISH];
__device__ __align__(16) __half g_eact16[(size_t)NTOK * TOPK * IDIM];
__device__ int   g_cnt[NEXP];
__device__ int   g_list[NEXP * NTOK];
__device__ float g_topw[NTOK * TOPK];
__device__ float g_gatesc[NTOK];

// ---------------- helpers ----------------
__device__ __forceinline__ uint32_t smem_u32(const void* p) {
    uint32_t a;
    asm("{ .reg .u64 t; cvta.to.shared.u64 t, %1; cvt.u32.u64 %0, t; }" : "=r"(a) : "l"(p));
    return a;
}
__device__ __forceinline__ void ldm4(uint32_t* r, uint32_t addr) {
    asm volatile("ldmatrix.sync.aligned.m8n8.x4.shared.b16 {%0,%1,%2,%3}, [%4];"
                 : "=r"(r[0]), "=r"(r[1]), "=r"(r[2]), "=r"(r[3]) : "r"(addr));
}
__device__ __forceinline__ void mma16(float* d, const uint32_t* a, uint32_t b0, uint32_t b1) {
    asm volatile(
        "mma.sync.aligned.m16n8k16.row.col.f32.f16.f16.f32 "
        "{%0,%1,%2,%3}, {%4,%5,%6,%7}, {%8,%9}, {%0,%1,%2,%3};"
        : "+f"(d[0]), "+f"(d[1]), "+f"(d[2]), "+f"(d[3])
        : "r"(a[0]), "r"(a[1]), "r"(a[2]), "r"(a[3]), "r"(b0), "r"(b1));
}
__device__ __forceinline__ void cp16(uint32_t dst, const void* src) {
    asm volatile("cp.async.cg.shared.global [%0], [%1], 16;" :: "r"(dst), "l"(src));
}
#define CP_COMMIT() asm volatile("cp.async.commit_group;" ::: "memory")
#define CP_WAIT2()  asm volatile("cp.async.wait_group 2;" ::: "memory")
__device__ __forceinline__ float silu_mul(float g, float u) {
    return g / (1.f + expf(-g)) * u;
}

// stage fill: each thread owns one row (tid), 64 bytes per stage
#define LOADSTAGE(st, k0)                                              \
    do {                                                               \
        uint32_t _d = sb + (uint32_t)(st) * STAGE_B + (uint32_t)tid * (RS * 2); \
        const __half* _s = mySrc + (k0);                               \
        cp16(_d, _s); cp16(_d + 16, _s + 8);                           \
        cp16(_d + 32, _s + 16); cp16(_d + 48, _s + 24);                \
    } while (0)

// ---------------- setup ----------------
__global__ void setup_kernel(float* out, int out_size) {
    int t = threadIdx.x;
    if (t < NEXP) g_cnt[t] = 0;
    if (t == 0)
        for (int i = NTOK * HDIM; i < out_size; i++) out[i] = (float)NEXP;  // aux = E exactly
}

// ---------------- fp32 -> fp16 conversion ----------------
__global__ void cvt_kernel(const float4* __restrict__ src, __half2* __restrict__ dst, int n4) {
    int i = blockIdx.x * blockDim.x + threadIdx.x;
    if (i < n4) {
        float4 v = src[i];
        dst[2 * i]     = __floats2half2_rn(v.x, v.y);
        dst[2 * i + 1] = __floats2half2_rn(v.z, v.w);
    }
}

// ---------------- router (fp32 exact) ----------------
__global__ void router_kernel(const float* __restrict__ h,
                              const float* __restrict__ rw,
                              const float* __restrict__ egw) {
    int n = blockIdx.x, tid = threadIdx.x, lane = tid & 31, w = tid >> 5;
    __shared__ float hs[HDIM];
    __shared__ float logits[NEXP + 1];
    const float4* hp = (const float4*)(h + (size_t)n * HDIM);
    float4* hs4 = (float4*)hs;
    for (int i = tid; i < HDIM / 4; i += 128) hs4[i] = hp[i];
    __syncthreads();
    for (int e = w; e < NEXP + 1; e += 4) {
        const float* wr = (e < NEXP) ? (rw + (size_t)e * HDIM) : egw;
        float s = 0.f;
        for (int i = lane; i < HDIM; i += 32) s += hs[i] * wr[i];
        for (int o = 16; o > 0; o >>= 1) s += __shfl_down_sync(0xffffffffu, s, o);
        if (lane == 0) logits[e] = s;
    }
    __syncthreads();
    if (tid == 0) {
        float mx = -1e30f;
        for (int e = 0; e < NEXP; e++) mx = fmaxf(mx, logits[e]);
        float p[NEXP], den = 0.f;
        for (int e = 0; e < NEXP; e++) { p[e] = expf(logits[e] - mx); den += p[e]; }
        float inv = 1.f / den;
        for (int e = 0; e < NEXP; e++) p[e] *= inv;
        int sel[TOPK]; float sv[TOPK]; float ssum = 0.f;
        for (int k = 0; k < TOPK; k++) {
            int bi = 0; float bv = -1.f;
            for (int e = 0; e < NEXP; e++) if (p[e] > bv) { bv = p[e]; bi = e; }
            sel[k] = bi; sv[k] = bv; ssum += bv; p[bi] = -2.f;
        }
        float rinv = 1.f / ssum;
        for (int k = 0; k < TOPK; k++) {
            int entry = n * TOPK + k;
            g_topw[entry] = sv[k] * rinv;
            int pos = atomicAdd(&g_cnt[sel[k]], 1);
            g_list[sel[k] * NTOK + pos] = entry;
        }
        g_gatesc[n] = 1.f / (1.f + expf(-logits[NEXP]));
    }
}

// =====================================================================
// fp16 m16n8k16 + ldmatrix GEMMs, 4-stage cp.async. NT layout.
// DUAL:   block 128(M)x64(N), 8 warps 4x2, warp 32x32, dual gate/up output.
// SINGLE: block 128(M)x128(N), 8 warps 2x4, warp 64x32.
// Stage: rows [0,128)=A, [128,256)=B (single) / [128,192)=G,[192,256)=U (dual).
// =====================================================================

// ---- shared gate/up (dual): g_sact16 = silu(h@Wg^T) * (h@Wu^T) ----
__global__ void __launch_bounds__(256, 2) k_dual_shared() {
    extern __shared__ char smc[];
    uint32_t sb = smem_u32(smc);
    const int tid = threadIdx.x, lane = tid & 31, w = tid >> 5;
    const int wm = w & 3, wn = w >> 2, g = lane >> 2, c = lane & 3;
    const int row0 = blockIdx.y * 128, col0 = blockIdx.x * 64;

    const __half* mySrc;
    if (tid < 128)       mySrc = g_h16   + (size_t)(row0 + tid) * HDIM;
    else if (tid < 192)  mySrc = g_sgw16 + (size_t)(col0 + tid - 128) * HDIM;
    else                 mySrc = g_suw16 + (size_t)(col0 + tid - 192) * HDIM;

    const uint32_t lmo = ((lane & 15) * RS + (lane >> 4) * 8) * 2;
    const uint32_t aB = sb + (uint32_t)(wm * 32) * 80 + lmo;
    const uint32_t gB = sb + (uint32_t)(128 + wn * 32) * 80 + lmo;
    const uint32_t uB = sb + (uint32_t)(192 + wn * 32) * 80 + lmo;

    LOADSTAGE(0, 0);  CP_COMMIT();
    LOADSTAGE(1, 32); CP_COMMIT();
    LOADSTAGE(2, 64); CP_COMMIT();

    float accg[2][4][4] = {}, accu[2][4][4] = {};
    const int NIT = HDIM / 32;
    for (int it = 0; it < NIT; it++) {
        CP_WAIT2();
        __syncthreads();
        if (it + 3 < NIT) LOADSTAGE((it + 3) & 3, (it + 3) * 32);
        CP_COMMIT();
        uint32_t so = (uint32_t)(it & 3) * STAGE_B;
#pragma unroll
        for (int ks = 0; ks < 2; ks++) {
            uint32_t af[2][4], gf[2][4], uf[2][4];
            ldm4(af[0], aB + so + ks * 32);
            ldm4(af[1], aB + so + 1280 + ks * 32);
            ldm4(gf[0], gB + so + ks * 32);
            ldm4(gf[1], gB + so + 1280 + ks * 32);
            ldm4(uf[0], uB + so + ks * 32);
            ldm4(uf[1], uB + so + 1280 + ks * 32);
#pragma unroll
            for (int mi = 0; mi < 2; mi++)
#pragma unroll
                for (int ni = 0; ni < 4; ni++) {
                    mma16(accg[mi][ni], af[mi], gf[ni >> 1][ni & 1], gf[ni >> 1][(ni & 1) + 2]);
                    mma16(accu[mi][ni], af[mi], uf[ni >> 1][ni & 1], uf[ni >> 1][(ni & 1) + 2]);
                }
        }
    }
#pragma unroll
    for (int mi = 0; mi < 2; mi++) {
        int r = row0 + wm * 32 + mi * 16 + g;
#pragma unroll
        for (int ni = 0; ni < 4; ni++) {
            int cc = col0 + wn * 32 + ni * 8 + 2 * c;
            *(half2*)&g_sact16[(size_t)r * ISH + cc] =
                __floats2half2_rn(silu_mul(accg[mi][ni][0], accu[mi][ni][0]),
                                  silu_mul(accg[mi][ni][1], accu[mi][ni][1]));
            *(half2*)&g_sact16[(size_t)(r + 8) * ISH + cc] =
                __floats2half2_rn(silu_mul(accg[mi][ni][2], accu[mi][ni][2]),
                                  silu_mul(accg[mi][ni][3], accu[mi][ni][3]));
        }
    }
}

// ---- shared down: out = gatesc * (g_sact16 @ sdw^T) ----
__global__ void __launch_bounds__(256, 2) k_single_shared(float* __restrict__ out) {
    extern __shared__ char smc[];
    uint32_t sb = smem_u32(smc);
    const int tid = threadIdx.x, lane = tid & 31, w = tid >> 5;
    const int wm = w & 1, wn = w >> 1, g = lane >> 2, c = lane & 3;
    const int row0 = blockIdx.y * 128, col0 = blockIdx.x * 128;

    const __half* mySrc;
    if (tid < 128) mySrc = g_sact16 + (size_t)(row0 + tid) * ISH;
    else           mySrc = g_sdw16  + (size_t)(col0 + tid - 128) * ISH;

    const uint32_t lmo = ((lane & 15) * RS + (lane >> 4) * 8) * 2;
    const uint32_t aB = sb + (uint32_t)(wm * 64) * 80 + lmo;
    const uint32_t bB = sb + (uint32_t)(128 + wn * 32) * 80 + lmo;

    LOADSTAGE(0, 0);  CP_COMMIT();
    LOADSTAGE(1, 32); CP_COMMIT();
    LOADSTAGE(2, 64); CP_COMMIT();

    float acc[4][4][4] = {};
    const int NIT = ISH / 32;
    for (int it = 0; it < NIT; it++) {
        CP_WAIT2();
        __syncthreads();
        if (it + 3 < NIT) LOADSTAGE((it + 3) & 3, (it + 3) * 32);
        CP_COMMIT();
        uint32_t so = (uint32_t)(it & 3) * STAGE_B;
#pragma unroll
        for (int ks = 0; ks < 2; ks++) {
            uint32_t af[4][4], bf[2][4];
#pragma unroll
            for (int mi = 0; mi < 4; mi++) ldm4(af[mi], aB + so + mi * 1280 + ks * 32);
#pragma unroll
            for (int nq = 0; nq < 2; nq++) ldm4(bf[nq], bB + so + nq * 1280 + ks * 32);
#pragma unroll
            for (int mi = 0; mi < 4; mi++)
#pragma unroll
                for (int ni = 0; ni < 4; ni++)
                    mma16(acc[mi][ni], af[mi], bf[ni >> 1][ni & 1], bf[ni >> 1][(ni & 1) + 2]);
        }
    }
#pragma unroll
    for (int mi = 0; mi < 4; mi++) {
        int r = row0 + wm * 64 + mi * 16 + g;
        float s0 = g_gatesc[r], s1 = g_gatesc[r + 8];
#pragma unroll
        for (int ni = 0; ni < 4; ni++) {
            int cc = col0 + wn * 32 + ni * 8 + 2 * c;
            float2 o0 = {s0 * acc[mi][ni][0], s0 * acc[mi][ni][1]};
            float2 o1 = {s1 * acc[mi][ni][2], s1 * acc[mi][ni][3]};
            *(float2*)&out[(size_t)r * HDIM + cc] = o0;
            *(float2*)&out[(size_t)(r + 8) * HDIM + cc] = o1;
        }
    }
}

// ---- expert gate/up (dual, gathered A rows): g_eact16[entry] = silu(g)*u ----
__global__ void __launch_bounds__(256, 2) k_dual_expert() {
    const int e = blockIdx.z;
    const int cnt = g_cnt[e];
    const int m0 = blockIdx.y * 128;
    if (m0 >= cnt) return;

    extern __shared__ char smc[];
    uint32_t sb = smem_u32(smc);
    __shared__ int ents[128];
    const int tid = threadIdx.x, lane = tid & 31, w = tid >> 5;
    const int wm = w & 3, wn = w >> 2, g = lane >> 2, c = lane & 3;
    const int col0 = blockIdx.x * 64;

    const __half* mySrc;
    if (tid < 128) {
        int r = min(m0 + tid, cnt - 1);
        int entry = g_list[e * NTOK + r];
        ents[tid] = entry;
        mySrc = g_h16 + (size_t)(entry >> 2) * HDIM;
    } else if (tid < 192) {
        mySrc = g_gup16 + ((size_t)e * 2 * IDIM + col0 + tid - 128) * HDIM;
    } else {
        mySrc = g_gup16 + ((size_t)e * 2 * IDIM + IDIM + col0 + tid - 192) * HDIM;
    }

    const uint32_t lmo = ((lane & 15) * RS + (lane >> 4) * 8) * 2;
    const uint32_t aB = sb + (uint32_t)(wm * 32) * 80 + lmo;
    const uint32_t gB = sb + (uint32_t)(128 + wn * 32) * 80 + lmo;
    const uint32_t uB = sb + (uint32_t)(192 + wn * 32) * 80 + lmo;

    LOADSTAGE(0, 0);  CP_COMMIT();
    LOADSTAGE(1, 32); CP_COMMIT();
    LOADSTAGE(2, 64); CP_COMMIT();

    float accg[2][4][4] = {}, accu[2][4][4] = {};
    const int NIT = HDIM / 32;
    for (int it = 0; it < NIT; it++) {
        CP_WAIT2();
        __syncthreads();
        if (it + 3 < NIT) LOADSTAGE((it + 3) & 3, (it + 3) * 32);
        CP_COMMIT();
        uint32_t so = (uint32_t)(it & 3) * STAGE_B;
#pragma unroll
        for (int ks = 0; ks < 2; ks++) {
            uint32_t af[2][4], gf[2][4], uf[2][4];
            ldm4(af[0], aB + so + ks * 32);
            ldm4(af[1], aB + so + 1280 + ks * 32);
            ldm4(gf[0], gB + so + ks * 32);
            ldm4(gf[1], gB + so + 1280 + ks * 32);
            ldm4(uf[0], uB + so + ks * 32);
            ldm4(uf[1], uB + so + 1280 + ks * 32);
#pragma unroll
            for (int mi = 0; mi < 2; mi++)
#pragma unroll
                for (int ni = 0; ni < 4; ni++) {
                    mma16(accg[mi][ni], af[mi], gf[ni >> 1][ni & 1], gf[ni >> 1][(ni & 1) + 2]);
                    mma16(accu[mi][ni], af[mi], uf[ni >> 1][ni & 1], uf[ni >> 1][(ni & 1) + 2]);
                }
        }
    }
#pragma unroll
    for (int mi = 0; mi < 2; mi++) {
        int rl0 = wm * 32 + mi * 16 + g;
        bool v0 = (m0 + rl0) < cnt, v1 = (m0 + rl0 + 8) < cnt;
        int e0 = ents[rl0], e1 = ents[rl0 + 8];
#pragma unroll
        for (int ni = 0; ni < 4; ni++) {
            int cc = col0 + wn * 32 + ni * 8 + 2 * c;
            if (v0)
                *(half2*)&g_eact16[(size_t)e0 * IDIM + cc] =
                    __floats2half2_rn(silu_mul(accg[mi][ni][0], accu[mi][ni][0]),
                                      silu_mul(accg[mi][ni][1], accu[mi][ni][1]));
            if (v1)
                *(half2*)&g_eact16[(size_t)e1 * IDIM + cc] =
                    __floats2half2_rn(silu_mul(accg[mi][ni][2], accu[mi][ni][2]),
                                      silu_mul(accg[mi][ni][3], accu[mi][ni][3]));
        }
    }
}

// ---- expert down (gathered A, atomic scatter): out += w * (g_eact16 @ dwn^T) ----
__global__ void __launch_bounds__(256, 2) k_single_expert(float* __restrict__ out) {
    const int e = blockIdx.z;
    const int cnt = g_cnt[e];
    const int m0 = blockIdx.y * 128;
    if (m0 >= cnt) return;

    extern __shared__ char smc[];
    uint32_t sb = smem_u32(smc);
    __shared__ int ents[128];
    const int tid = threadIdx.x, lane = tid & 31, w = tid >> 5;
    const int wm = w & 1, wn = w >> 1, g = lane >> 2, c = lane & 3;
    const int col0 = blockIdx.x * 128;

    const __half* mySrc;
    if (tid < 128) {
        int r = min(m0 + tid, cnt - 1);
        int entry = g_list[e * NTOK + r];
        ents[tid] = entry;
        mySrc = g_eact16 + (size_t)entry * IDIM;
    } else {
        mySrc = g_dwn16 + ((size_t)e * HDIM + col0 + tid - 128) * IDIM;
    }

    const uint32_t lmo = ((lane & 15) * RS + (lane >> 4) * 8) * 2;
    const uint32_t aB = sb + (uint32_t)(wm * 64) * 80 + lmo;
    const uint32_t bB = sb + (uint32_t)(128 + wn * 32) * 80 + lmo;

    LOADSTAGE(0, 0);  CP_COMMIT();
    LOADSTAGE(1, 32); CP_COMMIT();
    LOADSTAGE(2, 64); CP_COMMIT();

    float acc[4][4][4] = {};
    const int NIT = IDIM / 32;
    for (int it = 0; it < NIT; it++) {
        CP_WAIT2();
        __syncthreads();
        if (it + 3 < NIT) LOADSTAGE((it + 3) & 3, (it + 3) * 32);
        CP_COMMIT();
        uint32_t so = (uint32_t)(it & 3) * STAGE_B;
#pragma unroll
        for (int ks = 0; ks < 2; ks++) {
            uint32_t af[4][4], bf[2][4];
#pragma unroll
            for (int mi = 0; mi < 4; mi++) ldm4(af[mi], aB + so + mi * 1280 + ks * 32);
#pragma unroll
            for (int nq = 0; nq < 2; nq++) ldm4(bf[nq], bB + so + nq * 1280 + ks * 32);
#pragma unroll
            for (int mi = 0; mi < 4; mi++)
#pragma unroll
                for (int ni = 0; ni < 4; ni++)
                    mma16(acc[mi][ni], af[mi], bf[ni >> 1][ni & 1], bf[ni >> 1][(ni & 1) + 2]);
        }
    }
#pragma unroll
    for (int mi = 0; mi < 4; mi++) {
        int rl0 = wm * 64 + mi * 16 + g;
        bool v0 = (m0 + rl0) < cnt, v1 = (m0 + rl0 + 8) < cnt;
        int e0 = ents[rl0], e1 = ents[rl0 + 8];
        float w0 = v0 ? g_topw[e0] : 0.f;
        float w1 = v1 ? g_topw[e1] : 0.f;
        float* d0 = out + (size_t)(e0 >> 2) * HDIM;
        float* d1 = out + (size_t)(e1 >> 2) * HDIM;
#pragma unroll
        for (int ni = 0; ni < 4; ni++) {
            int cc = col0 + wn * 32 + ni * 8 + 2 * c;
            if (v0) {
                atomicAdd(d0 + cc, w0 * acc[mi][ni][0]);
                atomicAdd(d0 + cc + 1, w0 * acc[mi][ni][1]);
            }
            if (v1) {
                atomicAdd(d1 + cc, w1 * acc[mi][ni][2]);
                atomicAdd(d1 + cc + 1, w1 * acc[mi][ni][3]);
            }
        }
    }
}

// ---------------------------------------------------------------------------
static void cvt_launch(const float* src, __half* dst, size_t n) {
    int n4 = (int)(n / 4);
    cvt_kernel<<<(n4 + 255) / 256, 256>>>((const float4*)src, (__half2*)dst, n4);
}

extern "C" void kernel_launch(void* const* d_in, const int* in_sizes, int n_in,
                              void* d_out, int out_size) {
    const float* h    = (const float*)d_in[0];
    const float* rw   = (const float*)d_in[1];
    const float* gup  = (const float*)d_in[2];
    const float* dwn  = (const float*)d_in[3];
    const float* sgw  = (const float*)d_in[4];
    const float* suw  = (const float*)d_in[5];
    const float* sdw  = (const float*)d_in[6];
    const float* segw = (const float*)d_in[7];
    float* out = (float*)d_out;

    __half *p_h16, *p_gup16, *p_dwn16, *p_sgw16, *p_suw16, *p_sdw16;
    cudaGetSymbolAddress((void**)&p_h16, g_h16);
    cudaGetSymbolAddress((void**)&p_gup16, g_gup16);
    cudaGetSymbolAddress((void**)&p_dwn16, g_dwn16);
    cudaGetSymbolAddress((void**)&p_sgw16, g_sgw16);
    cudaGetSymbolAddress((void**)&p_suw16, g_suw16);
    cudaGetSymbolAddress((void**)&p_sdw16, g_sdw16);

    cudaFuncSetAttribute(k_dual_shared,   cudaFuncAttributeMaxDynamicSharedMemorySize, GEMM_SMEM);
    cudaFuncSetAttribute(k_dual_expert,   cudaFuncAttributeMaxDynamicSharedMemorySize, GEMM_SMEM);
    cudaFuncSetAttribute(k_single_shared, cudaFuncAttributeMaxDynamicSharedMemorySize, GEMM_SMEM);
    cudaFuncSetAttribute(k_single_expert, cudaFuncAttributeMaxDynamicSharedMemorySize, GEMM_SMEM);

    setup_kernel<<<1, 32>>>(out, out_size);
    cvt_launch(h,   p_h16,   (size_t)NTOK * HDIM);
    cvt_launch(gup, p_gup16, (size_t)NEXP * 2 * IDIM * HDIM);
    cvt_launch(dwn, p_dwn16, (size_t)NEXP * HDIM * IDIM);
    cvt_launch(sgw, p_sgw16, (size_t)ISH * HDIM);
    cvt_launch(suw, p_suw16, (size_t)ISH * HDIM);
    cvt_launch(sdw, p_sdw16, (size_t)HDIM * ISH);
    router_kernel<<<NTOK, 128>>>(h, rw, segw);

    k_dual_shared<<<dim3(ISH / 64, NTOK / 128), 256, GEMM_SMEM>>>();
    k_dual_expert<<<dim3(IDIM / 64, NTOK / 128, NEXP), 256, GEMM_SMEM>>>();
    k_single_shared<<<dim3(HDIM / 128, NTOK / 128), 256, GEMM_SMEM>>>(out);
    k_single_expert<<<dim3(HDIM / 128, NTOK / 128, NEXP), 256, GEMM_SMEM>>>(out);
}

// round 6
// speedup vs baseline: 5.4133x; 1.0672x over previous
#include <cuda_runtime.h>
#include <cuda_fp16.h>
#include <cstdint>
#include <math.h>

#define NTOK 4096
#define HDIM 1024
#define NEXP 16
#define IDIM 512
#define ISH  2048
#define TOPK 4

#define RS        40                       // halves per smem row stride (80 bytes)
#define STAGE_B   (256 * RS * 2)           // 20480 bytes per stage (256 rows)
#define NSTAGE    4
#define GEMM_SMEM (NSTAGE * STAGE_B)       // 81920 bytes

// ---------------- fp16 operand copies + scratch (device globals) ----------------
__device__ __align__(16) __half g_h16[(size_t)NTOK * HDIM];
__device__ __align__(16) __half g_gup16[(size_t)NEXP * 2 * IDIM * HDIM];
__device__ __align__(16) __half g_dwn16[(size_t)NEXP * HDIM * IDIM];
__device__ __align__(16) __half g_sgw16[(size_t)ISH * HDIM];
__device__ __align__(16) __half g_suw16[(size_t)ISH * HDIM];
__device__ __align__(16) __half g_sdw16[(size_t)HDIM * ISH];
__device__ __align__(16) __half g_sact16[(size_t)NTOK * ISH];
__device__ __align__(16) __half g_eact16[(size_t)NTOK * TOPK * IDIM];
__device__ int   g_cnt[NEXP];
__device__ int   g_list[NEXP * NTOK];
__device__ float g_topw[NTOK * TOPK];
__device__ float g_gatesc[NTOK];

// sizes (in float4 units) for the fused convert
#define N4_H    ((size_t)NTOK * HDIM / 4)
#define N4_GUP  ((size_t)NEXP * 2 * IDIM * HDIM / 4)
#define N4_DWN  ((size_t)NEXP * HDIM * IDIM / 4)
#define N4_SGW  ((size_t)ISH * HDIM / 4)
#define N4_SUW  ((size_t)ISH * HDIM / 4)
#define N4_SDW  ((size_t)HDIM * ISH / 4)
#define N4_TOT  (N4_H + N4_GUP + N4_DWN + N4_SGW + N4_SUW + N4_SDW)   // 8.5M

// ---------------- helpers ----------------
__device__ __forceinline__ uint32_t smem_u32(const void* p) {
    uint32_t a;
    asm("{ .reg .u64 t; cvta.to.shared.u64 t, %1; cvt.u32.u64 %0, t; }" : "=r"(a) : "l"(p));
    return a;
}
__device__ __forceinline__ void ldm4(uint32_t* r, uint32_t addr) {
    asm volatile("ldmatrix.sync.aligned.m8n8.x4.shared.b16 {%0,%1,%2,%3}, [%4];"
                 : "=r"(r[0]), "=r"(r[1]), "=r"(r[2]), "=r"(r[3]) : "r"(addr));
}
__device__ __forceinline__ void mma16(float* d, const uint32_t* a, uint32_t b0, uint32_t b1) {
    asm volatile(
        "mma.sync.aligned.m16n8k16.row.col.f32.f16.f16.f32 "
        "{%0,%1,%2,%3}, {%4,%5,%6,%7}, {%8,%9}, {%0,%1,%2,%3};"
        : "+f"(d[0]), "+f"(d[1]), "+f"(d[2]), "+f"(d[3])
        : "r"(a[0]), "r"(a[1]), "r"(a[2]), "r"(a[3]), "r"(b0), "r"(b1));
}
__device__ __forceinline__ void cp16(uint32_t dst, const void* src) {
    asm volatile("cp.async.cg.shared.global [%0], [%1], 16;" :: "r"(dst), "l"(src));
}
#define CP_COMMIT() asm volatile("cp.async.commit_group;" ::: "memory")
#define CP_WAIT2()  asm volatile("cp.async.wait_group 2;" ::: "memory")
__device__ __forceinline__ float silu_mul(float g, float u) {
    return g / (1.f + expf(-g)) * u;
}

// stage fill: each thread owns one row (tid), 64 bytes per stage
#define LOADSTAGE(st, k0)                                              \
    do {                                                               \
        uint32_t _d = sb + (uint32_t)(st) * STAGE_B + (uint32_t)tid * (RS * 2); \
        const __half* _s = mySrc + (k0);                               \
        cp16(_d, _s); cp16(_d + 16, _s + 8);                           \
        cp16(_d + 32, _s + 16); cp16(_d + 48, _s + 24);                \
    } while (0)

// ---------------- zero out + setup ----------------
__global__ void zero_kernel(float* out, int out_size) {
    int i = blockIdx.x * blockDim.x + threadIdx.x;
    if (i < NTOK * HDIM / 4) ((float4*)out)[i] = make_float4(0.f, 0.f, 0.f, 0.f);
    if (blockIdx.x == 0) {
        if (threadIdx.x < NEXP) g_cnt[threadIdx.x] = 0;
        if (threadIdx.x == 0)
            for (int k = NTOK * HDIM; k < out_size; k++) out[k] = (float)NEXP;  // aux = E exactly
    }
}

// ---------------- fused fp32 -> fp16 conversion (all 6 tensors) ----------------
__global__ void cvt_kernel(const float4* __restrict__ h,   const float4* __restrict__ gup,
                           const float4* __restrict__ dwn, const float4* __restrict__ sgw,
                           const float4* __restrict__ suw, const float4* __restrict__ sdw) {
    size_t i = (size_t)blockIdx.x * blockDim.x + threadIdx.x;
    if (i >= N4_TOT) return;
    const float4* src;
    __half2* dst;
    size_t o = i;
    if (o < N4_H)                    { src = h;   dst = (__half2*)g_h16; }
    else if ((o -= N4_H) < N4_GUP)   { src = gup; dst = (__half2*)g_gup16; }
    else if ((o -= N4_GUP) < N4_DWN) { src = dwn; dst = (__half2*)g_dwn16; }
    else if ((o -= N4_DWN) < N4_SGW) { src = sgw; dst = (__half2*)g_sgw16; }
    else if ((o -= N4_SGW) < N4_SUW) { src = suw; dst = (__half2*)g_suw16; }
    else { o -= N4_SUW;                src = sdw; dst = (__half2*)g_sdw16; }
    float4 v = src[o];
    dst[2 * o]     = __floats2half2_rn(v.x, v.y);
    dst[2 * o + 1] = __floats2half2_rn(v.z, v.w);
}

// ---------------- router (fp32 exact) ----------------
__global__ void router_kernel(const float* __restrict__ h,
                              const float* __restrict__ rw,
                              const float* __restrict__ egw) {
    int n = blockIdx.x, tid = threadIdx.x, lane = tid & 31, w = tid >> 5;
    __shared__ float hs[HDIM];
    __shared__ float logits[NEXP + 1];
    const float4* hp = (const float4*)(h + (size_t)n * HDIM);
    float4* hs4 = (float4*)hs;
    for (int i = tid; i < HDIM / 4; i += 128) hs4[i] = hp[i];
    __syncthreads();
    for (int e = w; e < NEXP + 1; e += 4) {
        const float* wr = (e < NEXP) ? (rw + (size_t)e * HDIM) : egw;
        float s = 0.f;
        for (int i = lane; i < HDIM; i += 32) s += hs[i] * wr[i];
        for (int o = 16; o > 0; o >>= 1) s += __shfl_down_sync(0xffffffffu, s, o);
        if (lane == 0) logits[e] = s;
    }
    __syncthreads();
    if (tid == 0) {
        float mx = -1e30f;
        for (int e = 0; e < NEXP; e++) mx = fmaxf(mx, logits[e]);
        float p[NEXP], den = 0.f;
        for (int e = 0; e < NEXP; e++) { p[e] = expf(logits[e] - mx); den += p[e]; }
        float inv = 1.f / den;
        for (int e = 0; e < NEXP; e++) p[e] *= inv;
        int sel[TOPK]; float sv[TOPK]; float ssum = 0.f;
        for (int k = 0; k < TOPK; k++) {
            int bi = 0; float bv = -1.f;
            for (int e = 0; e < NEXP; e++) if (p[e] > bv) { bv = p[e]; bi = e; }
            sel[k] = bi; sv[k] = bv; ssum += bv; p[bi] = -2.f;
        }
        float rinv = 1.f / ssum;
        for (int k = 0; k < TOPK; k++) {
            int entry = n * TOPK + k;
            g_topw[entry] = sv[k] * rinv;
            int pos = atomicAdd(&g_cnt[sel[k]], 1);
            g_list[sel[k] * NTOK + pos] = entry;
        }
        g_gatesc[n] = 1.f / (1.f + expf(-logits[NEXP]));
    }
}

// =====================================================================
// MERGED fp16 GEMMs (tail-filling): one dual kernel (shared + expert
// gate/up), one single kernel (shared + expert down, atomic into out).
// DUAL:   block 128(M)x64(N), 8 warps 4x2, warp 32x32 dual gate/up.
// SINGLE: block 128(M)x128(N), 8 warps 2x4, warp 64x32, runtime K.
// =====================================================================

#define DUAL_SH_BLKS  ((ISH / 64) * (NTOK / 128))                 // 1024
#define DUAL_EX_BLKS  ((IDIM / 64) * (NTOK / 128) * NEXP)         // 4096
#define SGL_SH_BLKS   ((HDIM / 128) * (NTOK / 128))               // 256
#define SGL_EX_BLKS   ((HDIM / 128) * (NTOK / 128) * NEXP)        // 4096

// ---- dual: gate/up for shared expert AND routed experts ----
__global__ void __launch_bounds__(256, 2) k_dual() {
    const int bid = blockIdx.x;
    const bool isSh = (bid < DUAL_SH_BLKS);
    int bx, by, e = 0, cnt = 0, m0 = 0, row0 = 0;
    if (isSh) {
        bx = bid & 31; by = bid >> 5;         // x: ISH/64=32, y: 32
        row0 = by * 128;
    } else {
        int t = bid - DUAL_SH_BLKS;
        e = t >> 8; int r = t & 255;          // per expert: 8 x * 32 y
        bx = r & 7; by = r >> 3;
        cnt = g_cnt[e];
        m0 = by * 128;
        if (m0 >= cnt) return;
    }
    const int col0 = bx * 64;

    extern __shared__ char smc[];
    uint32_t sb = smem_u32(smc);
    __shared__ int ents[128];
    const int tid = threadIdx.x, lane = tid & 31, w = tid >> 5;
    const int wm = w & 3, wn = w >> 2, g = lane >> 2, c = lane & 3;

    const __half* mySrc;
    if (isSh) {
        if (tid < 128)      mySrc = g_h16   + (size_t)(row0 + tid) * HDIM;
        else if (tid < 192) mySrc = g_sgw16 + (size_t)(col0 + tid - 128) * HDIM;
        else                mySrc = g_suw16 + (size_t)(col0 + tid - 192) * HDIM;
    } else {
        if (tid < 128) {
            int r = min(m0 + tid, cnt - 1);
            int entry = g_list[e * NTOK + r];
            ents[tid] = entry;
            mySrc = g_h16 + (size_t)(entry >> 2) * HDIM;
        } else if (tid < 192) {
            mySrc = g_gup16 + ((size_t)e * 2 * IDIM + col0 + tid - 128) * HDIM;
        } else {
            mySrc = g_gup16 + ((size_t)e * 2 * IDIM + IDIM + col0 + tid - 192) * HDIM;
        }
    }

    const uint32_t lmo = ((lane & 15) * RS + (lane >> 4) * 8) * 2;
    const uint32_t aB = sb + (uint32_t)(wm * 32) * 80 + lmo;
    const uint32_t gB = sb + (uint32_t)(128 + wn * 32) * 80 + lmo;
    const uint32_t uB = sb + (uint32_t)(192 + wn * 32) * 80 + lmo;

    LOADSTAGE(0, 0);  CP_COMMIT();
    LOADSTAGE(1, 32); CP_COMMIT();
    LOADSTAGE(2, 64); CP_COMMIT();

    float accg[2][4][4] = {}, accu[2][4][4] = {};
    const int NIT = HDIM / 32;
    for (int it = 0; it < NIT; it++) {
        CP_WAIT2();
        __syncthreads();
        if (it + 3 < NIT) LOADSTAGE((it + 3) & 3, (it + 3) * 32);
        CP_COMMIT();
        uint32_t so = (uint32_t)(it & 3) * STAGE_B;
#pragma unroll
        for (int ks = 0; ks < 2; ks++) {
            uint32_t af[2][4], gf[2][4], uf[2][4];
            ldm4(af[0], aB + so + ks * 32);
            ldm4(af[1], aB + so + 1280 + ks * 32);
            ldm4(gf[0], gB + so + ks * 32);
            ldm4(gf[1], gB + so + 1280 + ks * 32);
            ldm4(uf[0], uB + so + ks * 32);
            ldm4(uf[1], uB + so + 1280 + ks * 32);
#pragma unroll
            for (int mi = 0; mi < 2; mi++)
#pragma unroll
                for (int ni = 0; ni < 4; ni++) {
                    mma16(accg[mi][ni], af[mi], gf[ni >> 1][ni & 1], gf[ni >> 1][(ni & 1) + 2]);
                    mma16(accu[mi][ni], af[mi], uf[ni >> 1][ni & 1], uf[ni >> 1][(ni & 1) + 2]);
                }
        }
    }

    if (isSh) {
#pragma unroll
        for (int mi = 0; mi < 2; mi++) {
            int r = row0 + wm * 32 + mi * 16 + g;
#pragma unroll
            for (int ni = 0; ni < 4; ni++) {
                int cc = col0 + wn * 32 + ni * 8 + 2 * c;
                *(half2*)&g_sact16[(size_t)r * ISH + cc] =
                    __floats2half2_rn(silu_mul(accg[mi][ni][0], accu[mi][ni][0]),
                                      silu_mul(accg[mi][ni][1], accu[mi][ni][1]));
                *(half2*)&g_sact16[(size_t)(r + 8) * ISH + cc] =
                    __floats2half2_rn(silu_mul(accg[mi][ni][2], accu[mi][ni][2]),
                                      silu_mul(accg[mi][ni][3], accu[mi][ni][3]));
            }
        }
    } else {
#pragma unroll
        for (int mi = 0; mi < 2; mi++) {
            int rl0 = wm * 32 + mi * 16 + g;
            bool v0 = (m0 + rl0) < cnt, v1 = (m0 + rl0 + 8) < cnt;
            int e0 = ents[rl0], e1 = ents[rl0 + 8];
#pragma unroll
            for (int ni = 0; ni < 4; ni++) {
                int cc = col0 + wn * 32 + ni * 8 + 2 * c;
                if (v0)
                    *(half2*)&g_eact16[(size_t)e0 * IDIM + cc] =
                        __floats2half2_rn(silu_mul(accg[mi][ni][0], accu[mi][ni][0]),
                                          silu_mul(accg[mi][ni][1], accu[mi][ni][1]));
                if (v1)
                    *(half2*)&g_eact16[(size_t)e1 * IDIM + cc] =
                        __floats2half2_rn(silu_mul(accg[mi][ni][2], accu[mi][ni][2]),
                                          silu_mul(accg[mi][ni][3], accu[mi][ni][3]));
            }
        }
    }
}

// ---- single: down-proj for shared expert AND routed experts; atomic into out ----
__global__ void __launch_bounds__(256, 2) k_single(float* __restrict__ out) {
    const int bid = blockIdx.x;
    const bool isSh = (bid < SGL_SH_BLKS);
    int bx, by, e = 0, cnt = 0, m0 = 0, row0 = 0, NIT;
    if (isSh) {
        bx = bid & 7; by = bid >> 3;          // x: 8, y: 32
        row0 = by * 128;
        NIT = ISH / 32;                        // 64
    } else {
        int t = bid - SGL_SH_BLKS;
        e = t >> 8; int r = t & 255;
        bx = r & 7; by = r >> 3;
        cnt = g_cnt[e];
        m0 = by * 128;
        if (m0 >= cnt) return;
        NIT = IDIM / 32;                       // 16
    }
    const int col0 = bx * 128;

    extern __shared__ char smc[];
    uint32_t sb = smem_u32(smc);
    __shared__ int ents[128];
    const int tid = threadIdx.x, lane = tid & 31, w = tid >> 5;
    const int wm = w & 1, wn = w >> 1, g = lane >> 2, c = lane & 3;

    const __half* mySrc;
    if (isSh) {
        if (tid < 128) mySrc = g_sact16 + (size_t)(row0 + tid) * ISH;
        else           mySrc = g_sdw16  + (size_t)(col0 + tid - 128) * ISH;
    } else {
        if (tid < 128) {
            int r = min(m0 + tid, cnt - 1);
            int entry = g_list[e * NTOK + r];
            ents[tid] = entry;
            mySrc = g_eact16 + (size_t)entry * IDIM;
        } else {
            mySrc = g_dwn16 + ((size_t)e * HDIM + col0 + tid - 128) * IDIM;
        }
    }

    const uint32_t lmo = ((lane & 15) * RS + (lane >> 4) * 8) * 2;
    const uint32_t aB = sb + (uint32_t)(wm * 64) * 80 + lmo;
    const uint32_t bB = sb + (uint32_t)(128 + wn * 32) * 80 + lmo;

    LOADSTAGE(0, 0);  CP_COMMIT();
    LOADSTAGE(1, 32); CP_COMMIT();
    LOADSTAGE(2, 64); CP_COMMIT();

    float acc[4][4][4] = {};
    for (int it = 0; it < NIT; it++) {
        CP_WAIT2();
        __syncthreads();
        if (it + 3 < NIT) LOADSTAGE((it + 3) & 3, (it + 3) * 32);
        CP_COMMIT();
        uint32_t so = (uint32_t)(it & 3) * STAGE_B;
#pragma unroll
        for (int ks = 0; ks < 2; ks++) {
            uint32_t af[4][4], bf[2][4];
#pragma unroll
            for (int mi = 0; mi < 4; mi++) ldm4(af[mi], aB + so + mi * 1280 + ks * 32);
#pragma unroll
            for (int nq = 0; nq < 2; nq++) ldm4(bf[nq], bB + so + nq * 1280 + ks * 32);
#pragma unroll
            for (int mi = 0; mi < 4; mi++)
#pragma unroll
                for (int ni = 0; ni < 4; ni++)
                    mma16(acc[mi][ni], af[mi], bf[ni >> 1][ni & 1], bf[ni >> 1][(ni & 1) + 2]);
        }
    }

#pragma unroll
    for (int mi = 0; mi < 4; mi++) {
        int rl0 = wm * 64 + mi * 16 + g;
        bool v0, v1;
        float w0, w1;
        float *d0, *d1;
        if (isSh) {
            int r = row0 + rl0;
            v0 = v1 = true;
            w0 = g_gatesc[r]; w1 = g_gatesc[r + 8];
            d0 = out + (size_t)r * HDIM;
            d1 = out + (size_t)(r + 8) * HDIM;
        } else {
            v0 = (m0 + rl0) < cnt; v1 = (m0 + rl0 + 8) < cnt;
            int e0 = ents[rl0], e1 = ents[rl0 + 8];
            w0 = v0 ? g_topw[e0] : 0.f;
            w1 = v1 ? g_topw[e1] : 0.f;
            d0 = out + (size_t)(e0 >> 2) * HDIM;
            d1 = out + (size_t)(e1 >> 2) * HDIM;
        }
#pragma unroll
        for (int ni = 0; ni < 4; ni++) {
            int cc = col0 + wn * 32 + ni * 8 + 2 * c;
            if (v0) {
                atomicAdd(d0 + cc, w0 * acc[mi][ni][0]);
                atomicAdd(d0 + cc + 1, w0 * acc[mi][ni][1]);
            }
            if (v1) {
                atomicAdd(d1 + cc, w1 * acc[mi][ni][2]);
                atomicAdd(d1 + cc + 1, w1 * acc[mi][ni][3]);
            }
        }
    }
}

// ---------------------------------------------------------------------------
extern "C" void kernel_launch(void* const* d_in, const int* in_sizes, int n_in,
                              void* d_out, int out_size) {
    const float* h    = (const float*)d_in[0];
    const float* rw   = (const float*)d_in[1];
    const float* gup  = (const float*)d_in[2];
    const float* dwn  = (const float*)d_in[3];
    const float* sgw  = (const float*)d_in[4];
    const float* suw  = (const float*)d_in[5];
    const float* sdw  = (const float*)d_in[6];
    const float* segw = (const float*)d_in[7];
    float* out = (float*)d_out;

    cudaFuncSetAttribute(k_dual,   cudaFuncAttributeMaxDynamicSharedMemorySize, GEMM_SMEM);
    cudaFuncSetAttribute(k_single, cudaFuncAttributeMaxDynamicSharedMemorySize, GEMM_SMEM);

    zero_kernel<<<(NTOK * HDIM / 4 + 255) / 256, 256>>>(out, out_size);
    cvt_kernel<<<(int)((N4_TOT + 255) / 256), 256>>>(
        (const float4*)h, (const float4*)gup, (const float4*)dwn,
        (const float4*)sgw, (const float4*)suw, (const float4*)sdw);
    router_kernel<<<NTOK, 128>>>(h, rw, segw);

    k_dual<<<DUAL_SH_BLKS + DUAL_EX_BLKS, 256, GEMM_SMEM>>>();
    k_single<<<SGL_SH_BLKS + SGL_EX_BLKS, 256, GEMM_SMEM>>>(out);
}

// round 7
// speedup vs baseline: 5.7287x; 1.0583x over previous
#include <cuda_runtime.h>
#include <cuda_fp16.h>
#include <cstdint>
#include <math.h>

#define NTOK 4096
#define HDIM 1024
#define NEXP 16
#define IDIM 512
#define ISH  2048
#define TOPK 4

#define RS        40                       // halves per smem row stride (80 bytes)
#define STAGE_B   (384 * RS * 2)           // 30720 bytes per stage (384 rows)
#define NSTAGE    4
#define GEMM_SMEM (NSTAGE * STAGE_B)       // 122880 bytes

// ---------------- fp16 operand copies + scratch (device globals) ----------------
__device__ __align__(16) __half g_h16[(size_t)NTOK * HDIM];
__device__ __align__(16) __half g_gup16[(size_t)NEXP * 2 * IDIM * HDIM];
__device__ __align__(16) __half g_dwn16[(size_t)NEXP * HDIM * IDIM];
__device__ __align__(16) __half g_sgw16[(size_t)ISH * HDIM];
__device__ __align__(16) __half g_suw16[(size_t)ISH * HDIM];
__device__ __align__(16) __half g_sdw16[(size_t)HDIM * ISH];
__device__ __align__(16) __half g_sact16[(size_t)NTOK * ISH];
__device__ __align__(16) __half g_eact16[(size_t)NTOK * TOPK * IDIM];
__device__ int   g_cnt[NEXP];
__device__ int   g_list[NEXP * NTOK];
__device__ float g_topw[NTOK * TOPK];
__device__ float g_gatesc[NTOK];

// sizes (in float4 units) for the fused convert
#define N4_H    ((size_t)NTOK * HDIM / 4)
#define N4_GUP  ((size_t)NEXP * 2 * IDIM * HDIM / 4)
#define N4_DWN  ((size_t)NEXP * HDIM * IDIM / 4)
#define N4_SGW  ((size_t)ISH * HDIM / 4)
#define N4_SUW  ((size_t)ISH * HDIM / 4)
#define N4_SDW  ((size_t)HDIM * ISH / 4)
#define N4_TOT  (N4_H + N4_GUP + N4_DWN + N4_SGW + N4_SUW + N4_SDW)

// ---------------- helpers ----------------
__device__ __forceinline__ uint32_t smem_u32(const void* p) {
    uint32_t a;
    asm("{ .reg .u64 t; cvta.to.shared.u64 t, %1; cvt.u32.u64 %0, t; }" : "=r"(a) : "l"(p));
    return a;
}
__device__ __forceinline__ void ldm4(uint32_t* r, uint32_t addr) {
    asm volatile("ldmatrix.sync.aligned.m8n8.x4.shared.b16 {%0,%1,%2,%3}, [%4];"
                 : "=r"(r[0]), "=r"(r[1]), "=r"(r[2]), "=r"(r[3]) : "r"(addr));
}
__device__ __forceinline__ void mma16(float* d, const uint32_t* a, uint32_t b0, uint32_t b1) {
    asm volatile(
        "mma.sync.aligned.m16n8k16.row.col.f32.f16.f16.f32 "
        "{%0,%1,%2,%3}, {%4,%5,%6,%7}, {%8,%9}, {%0,%1,%2,%3};"
        : "+f"(d[0]), "+f"(d[1]), "+f"(d[2]), "+f"(d[3])
        : "r"(a[0]), "r"(a[1]), "r"(a[2]), "r"(a[3]), "r"(b0), "r"(b1));
}
__device__ __forceinline__ void cp16(uint32_t dst, const void* src) {
    asm volatile("cp.async.cg.shared.global [%0], [%1], 16;" :: "r"(dst), "l"(src));
}
#define CP_COMMIT() asm volatile("cp.async.commit_group;" ::: "memory")
#define CP_WAIT2()  asm volatile("cp.async.wait_group 2;" ::: "memory")
__device__ __forceinline__ float silu_mul(float g, float u) {
    return g / (1.f + expf(-g)) * u;
}

// stage fill: threads 0..383 each own one row; 64 bytes per stage
#define LOADSTAGE(st, k0)                                              \
    do {                                                               \
        if (tid < 384) {                                               \
            uint32_t _d = sb + (uint32_t)(st) * STAGE_B + (uint32_t)tid * (RS * 2); \
            const __half* _s = mySrc + (k0);                           \
            cp16(_d, _s); cp16(_d + 16, _s + 8);                       \
            cp16(_d + 32, _s + 16); cp16(_d + 48, _s + 24);            \
        }                                                              \
    } while (0)

// ---------------- zero out + setup ----------------
__global__ void zero_kernel(float* out, int out_size) {
    int i = blockIdx.x * blockDim.x + threadIdx.x;
    if (i < NTOK * HDIM / 4) ((float4*)out)[i] = make_float4(0.f, 0.f, 0.f, 0.f);
    if (blockIdx.x == 0) {
        if (threadIdx.x < NEXP) g_cnt[threadIdx.x] = 0;
        if (threadIdx.x == 0)
            for (int k = NTOK * HDIM; k < out_size; k++) out[k] = (float)NEXP;  // aux = E exactly
    }
}

// ---------------- fused fp32 -> fp16 conversion (all 6 tensors) ----------------
__global__ void cvt_kernel(const float4* __restrict__ h,   const float4* __restrict__ gup,
                           const float4* __restrict__ dwn, const float4* __restrict__ sgw,
                           const float4* __restrict__ suw, const float4* __restrict__ sdw) {
    size_t i = (size_t)blockIdx.x * blockDim.x + threadIdx.x;
    if (i >= N4_TOT) return;
    const float4* src;
    __half2* dst;
    size_t o = i;
    if (o < N4_H)                    { src = h;   dst = (__half2*)g_h16; }
    else if ((o -= N4_H) < N4_GUP)   { src = gup; dst = (__half2*)g_gup16; }
    else if ((o -= N4_GUP) < N4_DWN) { src = dwn; dst = (__half2*)g_dwn16; }
    else if ((o -= N4_DWN) < N4_SGW) { src = sgw; dst = (__half2*)g_sgw16; }
    else if ((o -= N4_SGW) < N4_SUW) { src = suw; dst = (__half2*)g_suw16; }
    else { o -= N4_SUW;                src = sdw; dst = (__half2*)g_sdw16; }
    float4 v = src[o];
    dst[2 * o]     = __floats2half2_rn(v.x, v.y);
    dst[2 * o + 1] = __floats2half2_rn(v.z, v.w);
}

// ---------------- router (fp32 exact) ----------------
__global__ void router_kernel(const float* __restrict__ h,
                              const float* __restrict__ rw,
                              const float* __restrict__ egw) {
    int n = blockIdx.x, tid = threadIdx.x, lane = tid & 31, w = tid >> 5;
    __shared__ float hs[HDIM];
    __shared__ float logits[NEXP + 1];
    const float4* hp = (const float4*)(h + (size_t)n * HDIM);
    float4* hs4 = (float4*)hs;
    for (int i = tid; i < HDIM / 4; i += 128) hs4[i] = hp[i];
    __syncthreads();
    for (int e = w; e < NEXP + 1; e += 4) {
        const float* wr = (e < NEXP) ? (rw + (size_t)e * HDIM) : egw;
        float s = 0.f;
        for (int i = lane; i < HDIM; i += 32) s += hs[i] * wr[i];
        for (int o = 16; o > 0; o >>= 1) s += __shfl_down_sync(0xffffffffu, s, o);
        if (lane == 0) logits[e] = s;
    }
    __syncthreads();
    if (tid == 0) {
        float mx = -1e30f;
        for (int e = 0; e < NEXP; e++) mx = fmaxf(mx, logits[e]);
        float p[NEXP], den = 0.f;
        for (int e = 0; e < NEXP; e++) { p[e] = expf(logits[e] - mx); den += p[e]; }
        float inv = 1.f / den;
        for (int e = 0; e < NEXP; e++) p[e] *= inv;
        int sel[TOPK]; float sv[TOPK]; float ssum = 0.f;
        for (int k = 0; k < TOPK; k++) {
            int bi = 0; float bv = -1.f;
            for (int e = 0; e < NEXP; e++) if (p[e] > bv) { bv = p[e]; bi = e; }
            sel[k] = bi; sv[k] = bv; ssum += bv; p[bi] = -2.f;
        }
        float rinv = 1.f / ssum;
        for (int k = 0; k < TOPK; k++) {
            int entry = n * TOPK + k;
            g_topw[entry] = sv[k] * rinv;
            int pos = atomicAdd(&g_cnt[sel[k]], 1);
            g_list[sel[k] * NTOK + pos] = entry;
        }
        g_gatesc[n] = 1.f / (1.f + expf(-logits[NEXP]));
    }
}

// =====================================================================
// 512-thread, 1 CTA/SM GEMMs with doubled tiles (L2-intensity fix).
// DUAL:   block 128(M)x128(N) dual gate/up, 16 warps 4x4, warp 32x32x2.
// SINGLE: block 128(M)x256(N), 16 warps 2x8, warp 64x32, runtime K.
// Stage rows: DUAL [0,128)=A [128,256)=G [256,384)=U;
//             SINGLE [0,128)=A [128,384)=B.
// =====================================================================

#define DUAL_SH_BLKS  ((ISH / 128) * (NTOK / 128))                // 512
#define DUAL_EX_BLKS  ((IDIM / 128) * (NTOK / 128) * NEXP)        // 2048
#define SGL_SH_BLKS   ((HDIM / 256) * (NTOK / 128))               // 128
#define SGL_EX_BLKS   ((HDIM / 256) * (NTOK / 128) * NEXP)        // 2048

// ---- dual: gate/up for shared expert AND routed experts ----
__global__ void __launch_bounds__(512, 1) k_dual() {
    const int bid = blockIdx.x;
    const bool isSh = (bid < DUAL_SH_BLKS);
    int bx, by, e = 0, cnt = 0, m0 = 0, row0 = 0;
    if (isSh) {
        bx = bid & 15; by = bid >> 4;          // x: ISH/128=16, y: 32
        row0 = by * 128;
    } else {
        int t = bid - DUAL_SH_BLKS;
        e = t >> 7; int r = t & 127;           // per expert: 4 x * 32 y
        bx = r & 3; by = r >> 2;
        cnt = g_cnt[e];
        m0 = by * 128;
        if (m0 >= cnt) return;
    }
    const int col0 = bx * 128;

    extern __shared__ char smc[];
    uint32_t sb = smem_u32(smc);
    __shared__ int ents[128];
    const int tid = threadIdx.x, lane = tid & 31, w = tid >> 5;
    const int wm = w & 3, wn = w >> 2, g = lane >> 2, c = lane & 3;

    const __half* mySrc = g_h16;
    if (isSh) {
        if (tid < 128)      mySrc = g_h16   + (size_t)(row0 + tid) * HDIM;
        else if (tid < 256) mySrc = g_sgw16 + (size_t)(col0 + tid - 128) * HDIM;
        else if (tid < 384) mySrc = g_suw16 + (size_t)(col0 + tid - 256) * HDIM;
    } else {
        if (tid < 128) {
            int r = min(m0 + tid, cnt - 1);
            int entry = g_list[e * NTOK + r];
            ents[tid] = entry;
            mySrc = g_h16 + (size_t)(entry >> 2) * HDIM;
        } else if (tid < 256) {
            mySrc = g_gup16 + ((size_t)e * 2 * IDIM + col0 + tid - 128) * HDIM;
        } else if (tid < 384) {
            mySrc = g_gup16 + ((size_t)e * 2 * IDIM + IDIM + col0 + tid - 256) * HDIM;
        }
    }

    const uint32_t lmo = ((lane & 15) * RS + (lane >> 4) * 8) * 2;
    const uint32_t aB = sb + (uint32_t)(wm * 32) * 80 + lmo;
    const uint32_t gB = sb + (uint32_t)(128 + wn * 32) * 80 + lmo;
    const uint32_t uB = sb + (uint32_t)(256 + wn * 32) * 80 + lmo;

    LOADSTAGE(0, 0);  CP_COMMIT();
    LOADSTAGE(1, 32); CP_COMMIT();
    LOADSTAGE(2, 64); CP_COMMIT();

    float accg[2][4][4] = {}, accu[2][4][4] = {};
    const int NIT = HDIM / 32;
    for (int it = 0; it < NIT; it++) {
        CP_WAIT2();
        __syncthreads();
        if (it + 3 < NIT) LOADSTAGE((it + 3) & 3, (it + 3) * 32);
        CP_COMMIT();
        uint32_t so = (uint32_t)(it & 3) * STAGE_B;
#pragma unroll
        for (int ks = 0; ks < 2; ks++) {
            uint32_t af[2][4], gf[2][4], uf[2][4];
            ldm4(af[0], aB + so + ks * 32);
            ldm4(af[1], aB + so + 1280 + ks * 32);
            ldm4(gf[0], gB + so + ks * 32);
            ldm4(gf[1], gB + so + 1280 + ks * 32);
            ldm4(uf[0], uB + so + ks * 32);
            ldm4(uf[1], uB + so + 1280 + ks * 32);
#pragma unroll
            for (int mi = 0; mi < 2; mi++)
#pragma unroll
                for (int ni = 0; ni < 4; ni++) {
                    mma16(accg[mi][ni], af[mi], gf[ni >> 1][ni & 1], gf[ni >> 1][(ni & 1) + 2]);
                    mma16(accu[mi][ni], af[mi], uf[ni >> 1][ni & 1], uf[ni >> 1][(ni & 1) + 2]);
                }
        }
    }

    if (isSh) {
#pragma unroll
        for (int mi = 0; mi < 2; mi++) {
            int r = row0 + wm * 32 + mi * 16 + g;
#pragma unroll
            for (int ni = 0; ni < 4; ni++) {
                int cc = col0 + wn * 32 + ni * 8 + 2 * c;
                *(half2*)&g_sact16[(size_t)r * ISH + cc] =
                    __floats2half2_rn(silu_mul(accg[mi][ni][0], accu[mi][ni][0]),
                                      silu_mul(accg[mi][ni][1], accu[mi][ni][1]));
                *(half2*)&g_sact16[(size_t)(r + 8) * ISH + cc] =
                    __floats2half2_rn(silu_mul(accg[mi][ni][2], accu[mi][ni][2]),
                                      silu_mul(accg[mi][ni][3], accu[mi][ni][3]));
            }
        }
    } else {
#pragma unroll
        for (int mi = 0; mi < 2; mi++) {
            int rl0 = wm * 32 + mi * 16 + g;
            bool v0 = (m0 + rl0) < cnt, v1 = (m0 + rl0 + 8) < cnt;
            int e0 = ents[rl0], e1 = ents[rl0 + 8];
#pragma unroll
            for (int ni = 0; ni < 4; ni++) {
                int cc = col0 + wn * 32 + ni * 8 + 2 * c;
                if (v0)
                    *(half2*)&g_eact16[(size_t)e0 * IDIM + cc] =
                        __floats2half2_rn(silu_mul(accg[mi][ni][0], accu[mi][ni][0]),
                                          silu_mul(accg[mi][ni][1], accu[mi][ni][1]));
                if (v1)
                    *(half2*)&g_eact16[(size_t)e1 * IDIM + cc] =
                        __floats2half2_rn(silu_mul(accg[mi][ni][2], accu[mi][ni][2]),
                                          silu_mul(accg[mi][ni][3], accu[mi][ni][3]));
            }
        }
    }
}

// ---- single: down-proj for shared expert AND routed experts; atomic into out ----
__global__ void __launch_bounds__(512, 1) k_single(float* __restrict__ out) {
    const int bid = blockIdx.x;
    const bool isSh = (bid < SGL_SH_BLKS);
    int bx, by, e = 0, cnt = 0, m0 = 0, row0 = 0, NIT;
    if (isSh) {
        bx = bid & 3; by = bid >> 2;           // x: HDIM/256=4, y: 32
        row0 = by * 128;
        NIT = ISH / 32;                        // 64
    } else {
        int t = bid - SGL_SH_BLKS;
        e = t >> 7; int r = t & 127;
        bx = r & 3; by = r >> 2;
        cnt = g_cnt[e];
        m0 = by * 128;
        if (m0 >= cnt) return;
        NIT = IDIM / 32;                       // 16
    }
    const int col0 = bx * 256;

    extern __shared__ char smc[];
    uint32_t sb = smem_u32(smc);
    __shared__ int ents[128];
    const int tid = threadIdx.x, lane = tid & 31, w = tid >> 5;
    const int wm = w & 1, wn = w >> 1, g = lane >> 2, c = lane & 3;

    const __half* mySrc = g_sact16;
    if (isSh) {
        if (tid < 128)      mySrc = g_sact16 + (size_t)(row0 + tid) * ISH;
        else if (tid < 384) mySrc = g_sdw16  + (size_t)(col0 + tid - 128) * ISH;
    } else {
        if (tid < 128) {
            int r = min(m0 + tid, cnt - 1);
            int entry = g_list[e * NTOK + r];
            ents[tid] = entry;
            mySrc = g_eact16 + (size_t)entry * IDIM;
        } else if (tid < 384) {
            mySrc = g_dwn16 + ((size_t)e * HDIM + col0 + tid - 128) * IDIM;
        }
    }

    const uint32_t lmo = ((lane & 15) * RS + (lane >> 4) * 8) * 2;
    const uint32_t aB = sb + (uint32_t)(wm * 64) * 80 + lmo;
    const uint32_t bB = sb + (uint32_t)(128 + wn * 32) * 80 + lmo;

    LOADSTAGE(0, 0);  CP_COMMIT();
    LOADSTAGE(1, 32); CP_COMMIT();
    LOADSTAGE(2, 64); CP_COMMIT();

    float acc[4][4][4] = {};
    for (int it = 0; it < NIT; it++) {
        CP_WAIT2();
        __syncthreads();
        if (it + 3 < NIT) LOADSTAGE((it + 3) & 3, (it + 3) * 32);
        CP_COMMIT();
        uint32_t so = (uint32_t)(it & 3) * STAGE_B;
#pragma unroll
        for (int ks = 0; ks < 2; ks++) {
            uint32_t af[4][4], bf[2][4];
#pragma unroll
            for (int mi = 0; mi < 4; mi++) ldm4(af[mi], aB + so + mi * 1280 + ks * 32);
#pragma unroll
            for (int nq = 0; nq < 2; nq++) ldm4(bf[nq], bB + so + nq * 1280 + ks * 32);
#pragma unroll
            for (int mi = 0; mi < 4; mi++)
#pragma unroll
                for (int ni = 0; ni < 4; ni++)
                    mma16(acc[mi][ni], af[mi], bf[ni >> 1][ni & 1], bf[ni >> 1][(ni & 1) + 2]);
        }
    }

#pragma unroll
    for (int mi = 0; mi < 4; mi++) {
        int rl0 = wm * 64 + mi * 16 + g;
        bool v0, v1;
        float w0, w1;
        float *d0, *d1;
        if (isSh) {
            int r = row0 + rl0;
            v0 = v1 = true;
            w0 = g_gatesc[r]; w1 = g_gatesc[r + 8];
            d0 = out + (size_t)r * HDIM;
            d1 = out + (size_t)(r + 8) * HDIM;
        } else {
            v0 = (m0 + rl0) < cnt; v1 = (m0 + rl0 + 8) < cnt;
            int e0 = ents[rl0], e1 = ents[rl0 + 8];
            w0 = v0 ? g_topw[e0] : 0.f;
            w1 = v1 ? g_topw[e1] : 0.f;
            d0 = out + (size_t)(e0 >> 2) * HDIM;
            d1 = out + (size_t)(e1 >> 2) * HDIM;
        }
#pragma unroll
        for (int ni = 0; ni < 4; ni++) {
            int cc = col0 + wn * 32 + ni * 8 + 2 * c;
            if (v0) {
                atomicAdd(d0 + cc, w0 * acc[mi][ni][0]);
                atomicAdd(d0 + cc + 1, w0 * acc[mi][ni][1]);
            }
            if (v1) {
                atomicAdd(d1 + cc, w1 * acc[mi][ni][2]);
                atomicAdd(d1 + cc + 1, w1 * acc[mi][ni][3]);
            }
        }
    }
}

// ---------------------------------------------------------------------------
extern "C" void kernel_launch(void* const* d_in, const int* in_sizes, int n_in,
                              void* d_out, int out_size) {
    const float* h    = (const float*)d_in[0];
    const float* rw   = (const float*)d_in[1];
    const float* gup  = (const float*)d_in[2];
    const float* dwn  = (const float*)d_in[3];
    const float* sgw  = (const float*)d_in[4];
    const float* suw  = (const float*)d_in[5];
    const float* sdw  = (const float*)d_in[6];
    const float* segw = (const float*)d_in[7];
    float* out = (float*)d_out;

    cudaFuncSetAttribute(k_dual,   cudaFuncAttributeMaxDynamicSharedMemorySize, GEMM_SMEM);
    cudaFuncSetAttribute(k_single, cudaFuncAttributeMaxDynamicSharedMemorySize, GEMM_SMEM);

    zero_kernel<<<(NTOK * HDIM / 4 + 255) / 256, 256>>>(out, out_size);
    cvt_kernel<<<(int)((N4_TOT + 255) / 256), 256>>>(
        (const float4*)h, (const float4*)gup, (const float4*)dwn,
        (const float4*)sgw, (const float4*)suw, (const float4*)sdw);
    router_kernel<<<NTOK, 128>>>(h, rw, segw);

    k_dual<<<DUAL_SH_BLKS + DUAL_EX_BLKS, 512, GEMM_SMEM>>>();
    k_single<<<SGL_SH_BLKS + SGL_EX_BLKS, 512, GEMM_SMEM>>>(out);
}